// round 1
// baseline (speedup 1.0000x reference)
#include <cuda_runtime.h>
#include <math.h>

#define B_  2
#define S_  2048
#define D_  1024
#define H_  16
#define HD_ 64
#define ROWS_ (B_*S_)   // 4096

// ---------------- scratch (device globals; no allocations) ----------------
__device__ float g_xn  [ROWS_*D_];        // 16 MB
__device__ float g_qkv [ROWS_*3*D_];      // 48 MB
__device__ float g_q   [B_*H_*S_*HD_];    // 16 MB
__device__ float g_k   [B_*H_*S_*HD_];    // 16 MB
__device__ float g_v   [B_*H_*S_*HD_];    // 16 MB
__device__ float g_attn[ROWS_*D_];        // 16 MB

// ---------------- kernel 1: LayerNorm over D=1024 ----------------
__global__ __launch_bounds__(256) void ln_kernel(
    const float* __restrict__ x, const float* __restrict__ g,
    const float* __restrict__ b, float* __restrict__ y)
{
    __shared__ float red[16];
    const int row = blockIdx.x, tid = threadIdx.x;
    const float* xr = x + (size_t)row * D_;
    float4 v = *(const float4*)(xr + (tid << 2));
    float s  = v.x + v.y + v.z + v.w;
    float ss = v.x*v.x + v.y*v.y + v.z*v.z + v.w*v.w;
#pragma unroll
    for (int off = 16; off; off >>= 1) {
        s  += __shfl_xor_sync(0xffffffffu, s,  off);
        ss += __shfl_xor_sync(0xffffffffu, ss, off);
    }
    if ((tid & 31) == 0) { red[tid >> 5] = s; red[8 + (tid >> 5)] = ss; }
    __syncthreads();
    if (tid < 8) {
        float a = red[tid], c = red[8 + tid];
#pragma unroll
        for (int off = 4; off; off >>= 1) {
            a += __shfl_xor_sync(0xffu, a, off);
            c += __shfl_xor_sync(0xffu, c, off);
        }
        if (tid == 0) { red[0] = a; red[8] = c; }
    }
    __syncthreads();
    const float mean = red[0] * (1.f / 1024.f);
    const float var  = red[8] * (1.f / 1024.f) - mean * mean;
    const float r    = rsqrtf(var + 1e-6f);
    float4 gv = *(const float4*)(g + (tid << 2));
    float4 bv = *(const float4*)(b + (tid << 2));
    float4 o;
    o.x = (v.x - mean) * r * gv.x + bv.x;
    o.y = (v.y - mean) * r * gv.y + bv.y;
    o.z = (v.z - mean) * r * gv.z + bv.z;
    o.w = (v.w - mean) * r * gv.w + bv.w;
    *(float4*)(y + (size_t)row * D_ + (tid << 2)) = o;
}

// ---------------- kernel 2/5: 128x128x8 SGEMM + bias ----------------
__global__ __launch_bounds__(256) void sgemm_bias_kernel(
    const float* __restrict__ A, const float* __restrict__ Bm,
    const float* __restrict__ bias, float* __restrict__ C,
    int M, int N, int K)
{
    __shared__ float As[8][128];
    __shared__ float Bs[8][128];
    const int tid = threadIdx.x;
    const int tx = tid & 15, ty = tid >> 4;
    const int m0 = blockIdx.y << 7, n0 = blockIdx.x << 7;

    float acc[8][8];
#pragma unroll
    for (int i = 0; i < 8; i++)
#pragma unroll
        for (int j = 0; j < 8; j++) acc[i][j] = 0.f;

    const int lam = tid >> 1;            // 0..127 (row within A tile)
    const int lak = (tid & 1) << 2;      // 0 or 4
    const int lbk = tid >> 5;            // 0..7
    const int lbn = (tid & 31) << 2;     // 0..124
    const float* Ap = A  + (size_t)(m0 + lam) * K + lak;
    const float* Bp = Bm + (size_t)lbk * N + n0 + lbn;

    for (int k0 = 0; k0 < K; k0 += 8) {
        float4 av = *(const float4*)(Ap + k0);
        float4 bv = *(const float4*)(Bp + (size_t)k0 * N);
        __syncthreads();
        As[lak + 0][lam] = av.x; As[lak + 1][lam] = av.y;
        As[lak + 2][lam] = av.z; As[lak + 3][lam] = av.w;
        *(float4*)&Bs[lbk][lbn] = bv;
        __syncthreads();
#pragma unroll
        for (int kk = 0; kk < 8; ++kk) {
            float a[8], bb[8];
            float4 t;
            t = *(const float4*)&As[kk][(ty << 2)];      a[0]=t.x; a[1]=t.y; a[2]=t.z; a[3]=t.w;
            t = *(const float4*)&As[kk][64 + (ty << 2)]; a[4]=t.x; a[5]=t.y; a[6]=t.z; a[7]=t.w;
            t = *(const float4*)&Bs[kk][(tx << 2)];      bb[0]=t.x; bb[1]=t.y; bb[2]=t.z; bb[3]=t.w;
            t = *(const float4*)&Bs[kk][64 + (tx << 2)]; bb[4]=t.x; bb[5]=t.y; bb[6]=t.z; bb[7]=t.w;
#pragma unroll
            for (int i = 0; i < 8; i++)
#pragma unroll
                for (int j = 0; j < 8; j++)
                    acc[i][j] = fmaf(a[i], bb[j], acc[i][j]);
        }
    }
#pragma unroll
    for (int ri = 0; ri < 2; ++ri)
#pragma unroll
        for (int i = 0; i < 4; ++i) {
            int row = m0 + ri * 64 + (ty << 2) + i;
#pragma unroll
            for (int ci = 0; ci < 2; ++ci) {
                int col = n0 + ci * 64 + (tx << 2);
                float4 bb4 = *(const float4*)(bias + col);
                float4 o;
                o.x = acc[ri*4 + i][ci*4 + 0] + bb4.x;
                o.y = acc[ri*4 + i][ci*4 + 1] + bb4.y;
                o.z = acc[ri*4 + i][ci*4 + 2] + bb4.z;
                o.w = acc[ri*4 + i][ci*4 + 3] + bb4.w;
                *(float4*)(C + (size_t)row * N + col) = o;
            }
        }
}

// ---------------- kernel 3: per-head LN + RoPE + layout ----------------
__device__ __forceinline__ float warp_allreduce_sum(float v) {
#pragma unroll
    for (int off = 16; off; off >>= 1) v += __shfl_xor_sync(0xffffffffu, v, off);
    return v;
}

__global__ __launch_bounds__(512) void qk_rope_kernel(
    const float* __restrict__ qkv,
    const float* __restrict__ qsc, const float* __restrict__ ksc,
    float* __restrict__ Qo, float* __restrict__ Ko, float* __restrict__ Vo)
{
    const int bs   = blockIdx.x;          // b*S + s
    const int b    = bs >> 11;            // / 2048
    const int s    = bs & (S_ - 1);
    const int h    = threadIdx.x >> 5;    // warp = head
    const int lane = threadIdx.x & 31;
    const float* base = qkv + (size_t)bs * (3 * D_) + h * HD_;

    float q0 = base[lane],        q1 = base[lane + 32];
    float k0 = base[1024 + lane], k1 = base[1024 + lane + 32];
    float v0 = base[2048 + lane], v1 = base[2048 + lane + 32];

    // LN(q), scale only
    float mu  = warp_allreduce_sum(q0 + q1) * (1.f / 64.f);
    float d0  = q0 - mu, d1 = q1 - mu;
    float var = warp_allreduce_sum(d0*d0 + d1*d1) * (1.f / 64.f);
    float r   = rsqrtf(var + 1e-6f);
    float qn0 = d0 * r * qsc[lane];
    float qn1 = d1 * r * qsc[lane + 32];

    // LN(k)
    mu  = warp_allreduce_sum(k0 + k1) * (1.f / 64.f);
    d0  = k0 - mu; d1 = k1 - mu;
    var = warp_allreduce_sum(d0*d0 + d1*d1) * (1.f / 64.f);
    r   = rsqrtf(var + 1e-6f);
    float kn0 = d0 * r * ksc[lane];
    float kn1 = d1 * r * ksc[lane + 32];

    // RoPE: inv_freq = 10000^(-lane/32); angle = s * inv_freq (fp64 for accuracy)
    double invf = exp(-0.28782313662425575 * (double)lane); // ln(10000)/32
    double ang  = (double)s * invf;
    double sn, cs;
    sincos(ang, &sn, &cs);
    const float c  = (float)cs, si = (float)sn;

    float qr0 = qn0 * c - qn1 * si;
    float qr1 = qn1 * c + qn0 * si;
    float kr0 = kn0 * c - kn1 * si;
    float kr1 = kn1 * c + kn0 * si;

    const size_t o = (((size_t)(b * H_ + h)) * S_ + s) * HD_ + lane;
    Qo[o] = qr0; Qo[o + 32] = qr1;
    Ko[o] = kr0; Ko[o + 32] = kr1;
    Vo[o] = v0;  Vo[o + 32] = v1;
}

// ---------------- kernel 4: flash attention (64q x 64k tiles) ----------------
__global__ __launch_bounds__(256) void attn_kernel(
    const float* __restrict__ Q, const float* __restrict__ K,
    const float* __restrict__ V, float* __restrict__ O)
{
    constexpr int P = 68;  // smem pitch (floats)
    extern __shared__ float sm[];
    float* Qt = sm;                // [d][m] k-major
    float* Kt = sm + 64 * P;       // [d][n] k-major
    float* Vs = sm + 2 * 64 * P;   // [n][d]
    float* Ps = sm + 3 * 64 * P;   // [m][n]

    const int tid = threadIdx.x;
    const int tx = tid & 15, ty = tid >> 4;
    const int bh = blockIdx.y;
    const int q0 = blockIdx.x << 6;
    const float* Qb = Q + ((size_t)bh * S_ + q0) * HD_;
    const float* Kb = K + (size_t)bh * S_ * HD_;
    const float* Vb = V + (size_t)bh * S_ * HD_;

    const int lm  = tid >> 2;        // 0..63 row
    const int ld0 = (tid & 3) << 4;  // 0,16,32,48

    // load Q tile transposed (once)
#pragma unroll
    for (int u = 0; u < 4; ++u) {
        float4 t = *(const float4*)(Qb + (size_t)lm * HD_ + ld0 + (u << 2));
        Qt[(ld0 + (u << 2) + 0) * P + lm] = t.x;
        Qt[(ld0 + (u << 2) + 1) * P + lm] = t.y;
        Qt[(ld0 + (u << 2) + 2) * P + lm] = t.z;
        Qt[(ld0 + (u << 2) + 3) * P + lm] = t.w;
    }

    float m_[4], l_[4], o_[4][4];
#pragma unroll
    for (int i = 0; i < 4; i++) {
        m_[i] = -3.0e38f; l_[i] = 0.f;
#pragma unroll
        for (int j = 0; j < 4; j++) o_[i][j] = 0.f;
    }

    for (int kt = 0; kt < S_; kt += 64) {
        __syncthreads();  // previous tile fully consumed (also covers Q store, iter 0)
#pragma unroll
        for (int u = 0; u < 4; ++u) {
            float4 t = *(const float4*)(Kb + (size_t)(kt + lm) * HD_ + ld0 + (u << 2));
            Kt[(ld0 + (u << 2) + 0) * P + lm] = t.x;
            Kt[(ld0 + (u << 2) + 1) * P + lm] = t.y;
            Kt[(ld0 + (u << 2) + 2) * P + lm] = t.z;
            Kt[(ld0 + (u << 2) + 3) * P + lm] = t.w;
            float4 tv = *(const float4*)(Vb + (size_t)(kt + lm) * HD_ + ld0 + (u << 2));
            *(float4*)(Vs + lm * P + ld0 + (u << 2)) = tv;
        }
        __syncthreads();

        // S = Q K^T (64x64), thread owns 4x4
        float acc[4][4];
#pragma unroll
        for (int i = 0; i < 4; i++)
#pragma unroll
            for (int j = 0; j < 4; j++) acc[i][j] = 0.f;

#pragma unroll 8
        for (int kk = 0; kk < 64; ++kk) {
            float4 a4 = *(const float4*)(Qt + kk * P + (ty << 2));
            float4 b4 = *(const float4*)(Kt + kk * P + (tx << 2));
            float a[4]  = { a4.x, a4.y, a4.z, a4.w };
            float bb[4] = { b4.x, b4.y, b4.z, b4.w };
#pragma unroll
            for (int i = 0; i < 4; i++)
#pragma unroll
                for (int j = 0; j < 4; j++)
                    acc[i][j] = fmaf(a[i], bb[j], acc[i][j]);
        }

        // online softmax (each q row owned by one 16-lane group)
#pragma unroll
        for (int i = 0; i < 4; i++) {
#pragma unroll
            for (int j = 0; j < 4; j++) acc[i][j] *= 0.125f;  // 1/sqrt(64)
            float tm = fmaxf(fmaxf(acc[i][0], acc[i][1]), fmaxf(acc[i][2], acc[i][3]));
#pragma unroll
            for (int off = 1; off < 16; off <<= 1)
                tm = fmaxf(tm, __shfl_xor_sync(0xffffffffu, tm, off, 16));
            float mn = fmaxf(m_[i], tm);
            float al = expf(m_[i] - mn);
            m_[i] = mn;
            float p[4], rs = 0.f;
#pragma unroll
            for (int j = 0; j < 4; j++) { p[j] = expf(acc[i][j] - mn); rs += p[j]; }
#pragma unroll
            for (int off = 1; off < 16; off <<= 1)
                rs += __shfl_xor_sync(0xffffffffu, rs, off, 16);
            l_[i] = l_[i] * al + rs;
#pragma unroll
            for (int j = 0; j < 4; j++) o_[i][j] *= al;
            float4 p4 = { p[0], p[1], p[2], p[3] };
            *(float4*)(Ps + ((ty << 2) + i) * P + (tx << 2)) = p4;
        }
        __syncthreads();

        // O += P V (64x64 x 64x64)
#pragma unroll
        for (int kk = 0; kk < 64; kk += 4) {
            float pr[4][4];
#pragma unroll
            for (int i = 0; i < 4; i++) {
                float4 t = *(const float4*)(Ps + ((ty << 2) + i) * P + kk);
                pr[i][0] = t.x; pr[i][1] = t.y; pr[i][2] = t.z; pr[i][3] = t.w;
            }
#pragma unroll
            for (int u = 0; u < 4; u++) {
                float4 v4 = *(const float4*)(Vs + (kk + u) * P + (tx << 2));
                float vv[4] = { v4.x, v4.y, v4.z, v4.w };
#pragma unroll
                for (int i = 0; i < 4; i++)
#pragma unroll
                    for (int j = 0; j < 4; j++)
                        o_[i][j] = fmaf(pr[i][u], vv[j], o_[i][j]);
            }
        }
    }

    // epilogue: divide by l, write to [b, s, h*64+d]
    const int b = bh >> 4, h = bh & 15;
#pragma unroll
    for (int i = 0; i < 4; i++) {
        float inv = 1.0f / l_[i];
        int row = q0 + (ty << 2) + i;
        float4 o4 = { o_[i][0]*inv, o_[i][1]*inv, o_[i][2]*inv, o_[i][3]*inv };
        *(float4*)(O + ((size_t)(b * S_ + row)) * D_ + h * HD_ + (tx << 2)) = o4;
    }
}

// ---------------- launch ----------------
extern "C" void kernel_launch(void* const* d_in, const int* in_sizes, int n_in,
                              void* d_out, int out_size)
{
    const float* x        = (const float*)d_in[0];
    const float* w_qkv    = (const float*)d_in[1];
    const float* b_qkv    = (const float*)d_in[2];
    const float* w_out    = (const float*)d_in[3];
    const float* b_out    = (const float*)d_in[4];
    const float* ln_scale = (const float*)d_in[5];
    const float* ln_bias  = (const float*)d_in[6];
    const float* q_scale  = (const float*)d_in[7];
    const float* k_scale  = (const float*)d_in[8];
    float* out = (float*)d_out;

    float *xn, *qkv, *q, *k, *v, *attn;
    cudaGetSymbolAddress((void**)&xn,   g_xn);
    cudaGetSymbolAddress((void**)&qkv,  g_qkv);
    cudaGetSymbolAddress((void**)&q,    g_q);
    cudaGetSymbolAddress((void**)&k,    g_k);
    cudaGetSymbolAddress((void**)&v,    g_v);
    cudaGetSymbolAddress((void**)&attn, g_attn);

    const int attn_smem = 4 * 64 * 68 * sizeof(float); // 69632 B
    cudaFuncSetAttribute(attn_kernel, cudaFuncAttributeMaxDynamicSharedMemorySize, attn_smem);

    ln_kernel<<<ROWS_, 256>>>(x, ln_scale, ln_bias, xn);
    sgemm_bias_kernel<<<dim3((3 * D_) / 128, ROWS_ / 128), 256>>>(
        xn, w_qkv, b_qkv, qkv, ROWS_, 3 * D_, D_);
    qk_rope_kernel<<<ROWS_, 512>>>(qkv, q_scale, k_scale, q, k, v);
    attn_kernel<<<dim3(S_ / 64, B_ * H_), 256, attn_smem>>>(q, k, v, attn);
    sgemm_bias_kernel<<<dim3(D_ / 128, ROWS_ / 128), 256>>>(
        attn, w_out, b_out, out, ROWS_, D_, D_);
}

// round 4
// speedup vs baseline: 1.3666x; 1.3666x over previous
#include <cuda_runtime.h>
#include <stdint.h>
#include <math.h>

#define B_  2
#define S_  2048
#define D_  1024
#define H_  16
#define HD_ 64
#define ROWS_ (B_*S_)   // 4096

// ---------------- scratch (device globals; no allocations) ----------------
__device__ float g_xn  [ROWS_*D_];        // 16 MB
__device__ float g_qkv [ROWS_*3*D_];      // 48 MB
__device__ float g_q   [B_*H_*S_*HD_];    // 16 MB
__device__ float g_k   [B_*H_*S_*HD_];    // 16 MB
__device__ float g_v   [B_*H_*S_*HD_];    // 16 MB
__device__ float g_attn[ROWS_*D_];        // 16 MB

// ---------------- kernel 1: LayerNorm over D=1024 ----------------
__global__ __launch_bounds__(256) void ln_kernel(
    const float* __restrict__ x, const float* __restrict__ g,
    const float* __restrict__ b, float* __restrict__ y)
{
    __shared__ float red[16];
    const int row = blockIdx.x, tid = threadIdx.x;
    const float* xr = x + (size_t)row * D_;
    float4 v = *(const float4*)(xr + (tid << 2));
    float s  = v.x + v.y + v.z + v.w;
    float ss = v.x*v.x + v.y*v.y + v.z*v.z + v.w*v.w;
#pragma unroll
    for (int off = 16; off; off >>= 1) {
        s  += __shfl_xor_sync(0xffffffffu, s,  off);
        ss += __shfl_xor_sync(0xffffffffu, ss, off);
    }
    if ((tid & 31) == 0) { red[tid >> 5] = s; red[8 + (tid >> 5)] = ss; }
    __syncthreads();
    if (tid < 8) {
        float a = red[tid], c = red[8 + tid];
#pragma unroll
        for (int off = 4; off; off >>= 1) {
            a += __shfl_xor_sync(0xffu, a, off);
            c += __shfl_xor_sync(0xffu, c, off);
        }
        if (tid == 0) { red[0] = a; red[8] = c; }
    }
    __syncthreads();
    const float mean = red[0] * (1.f / 1024.f);
    const float var  = red[8] * (1.f / 1024.f) - mean * mean;
    const float r    = rsqrtf(var + 1e-6f);
    float4 gv = *(const float4*)(g + (tid << 2));
    float4 bv = *(const float4*)(b + (tid << 2));
    float4 o;
    o.x = (v.x - mean) * r * gv.x + bv.x;
    o.y = (v.y - mean) * r * gv.y + bv.y;
    o.z = (v.z - mean) * r * gv.z + bv.z;
    o.w = (v.w - mean) * r * gv.w + bv.w;
    *(float4*)(y + (size_t)row * D_ + (tid << 2)) = o;
}

// ---------------- tf32 helpers ----------------
__device__ __forceinline__ uint32_t f2tf32(float x) {
    uint32_t r;
    asm("cvt.rna.tf32.f32 %0, %1;" : "=r"(r) : "f"(x));
    return r;
}

#define MMA_TF32(d, a, b)                                              \
    asm volatile("mma.sync.aligned.m16n8k8.row.col.f32.tf32.tf32.f32 " \
        "{%0,%1,%2,%3}, {%4,%5,%6,%7}, {%8,%9}, {%0,%1,%2,%3};"        \
        : "+f"((d)[0]), "+f"((d)[1]), "+f"((d)[2]), "+f"((d)[3])       \
        : "r"((a)[0]), "r"((a)[1]), "r"((a)[2]), "r"((a)[3]),          \
          "r"((b)[0]), "r"((b)[1]))

// ---------------- kernel 2/5: tf32 tensor-core GEMM + bias ----------------
// C[M,N] = A[M,K] @ B[K,N] + bias.  128x128 CTA tile, 8 warps of 64x32,
// K-step 16, double-buffered smem.
__global__ __launch_bounds__(256) void tf32_gemm_bias(
    const float* __restrict__ A, const float* __restrict__ Bm,
    const float* __restrict__ bias, float* __restrict__ C,
    int M, int N, int K)
{
    constexpr int AP = 20;   // A smem pitch (floats): conflict-free frag reads
    constexpr int BP = 136;  // B smem pitch
    __shared__ uint32_t As[2][128 * AP];
    __shared__ uint32_t Bs[2][16 * BP];

    const int tid  = threadIdx.x;
    const int wid  = tid >> 5, lane = tid & 31;
    const int g    = lane >> 2, t = lane & 3;   // groupID, threadID_in_group
    const int wm   = wid & 1;                   // warp row (0..1) -> 64 rows
    const int wn   = wid >> 1;                  // warp col (0..3) -> 32 cols
    const int m0   = blockIdx.y << 7, n0 = blockIdx.x << 7;

    // gmem load mapping
    const int ar = tid >> 1;           // A row 0..127
    const int ac = (tid & 1) << 3;     // A col 0 or 8
    const int br = tid >> 4;           // B row 0..15
    const int bc = (tid & 15) << 2;    // B col 0..60 (and +64)

    const float* Ag = A  + (size_t)(m0 + ar) * K + ac;
    const float* Bg = Bm + (size_t)br * N + n0 + bc;

    float acc[4][4][4];
#pragma unroll
    for (int mi = 0; mi < 4; mi++)
#pragma unroll
        for (int ni = 0; ni < 4; ni++)
#pragma unroll
            for (int r = 0; r < 4; r++) acc[mi][ni][r] = 0.f;

    // prefetch first K-step
    float4 a0v = *(const float4*)(Ag);
    float4 a1v = *(const float4*)(Ag + 4);
    float4 b0v = *(const float4*)(Bg);
    float4 b1v = *(const float4*)(Bg + 64);

    const int KSTEPS = K >> 4;
    int buf = 0;
    for (int ks = 0; ks < KSTEPS; ++ks) {
        // store staged regs (tf32-rounded) to smem[buf]
        {
            uint32_t* p = &As[buf][ar * AP + ac];
            p[0] = f2tf32(a0v.x); p[1] = f2tf32(a0v.y);
            p[2] = f2tf32(a0v.z); p[3] = f2tf32(a0v.w);
            p[4] = f2tf32(a1v.x); p[5] = f2tf32(a1v.y);
            p[6] = f2tf32(a1v.z); p[7] = f2tf32(a1v.w);
            uint32_t* q = &Bs[buf][br * BP + bc];
            q[0]  = f2tf32(b0v.x); q[1]  = f2tf32(b0v.y);
            q[2]  = f2tf32(b0v.z); q[3]  = f2tf32(b0v.w);
            q[64] = f2tf32(b1v.x); q[65] = f2tf32(b1v.y);
            q[66] = f2tf32(b1v.z); q[67] = f2tf32(b1v.w);
        }
        __syncthreads();

        // prefetch next K-step
        if (ks + 1 < KSTEPS) {
            const float* Ap = Ag + (ks + 1) * 16;
            const float* Bp = Bg + (size_t)(ks + 1) * 16 * N;
            a0v = *(const float4*)(Ap);
            a1v = *(const float4*)(Ap + 4);
            b0v = *(const float4*)(Bp);
            b1v = *(const float4*)(Bp + 64);
        }

        // compute: 2 k-slices of 8
#pragma unroll
        for (int kk = 0; kk < 16; kk += 8) {
            uint32_t af[4][4], bfr[4][2];
#pragma unroll
            for (int mi = 0; mi < 4; mi++) {
                const int rb = wm * 64 + mi * 16;
                af[mi][0] = As[buf][(rb + g)     * AP + kk + t];
                af[mi][1] = As[buf][(rb + 8 + g) * AP + kk + t];
                af[mi][2] = As[buf][(rb + g)     * AP + kk + t + 4];
                af[mi][3] = As[buf][(rb + 8 + g) * AP + kk + t + 4];
            }
#pragma unroll
            for (int ni = 0; ni < 4; ni++) {
                const int cb = wn * 32 + ni * 8 + g;
                bfr[ni][0] = Bs[buf][(kk + t)     * BP + cb];
                bfr[ni][1] = Bs[buf][(kk + t + 4) * BP + cb];
            }
#pragma unroll
            for (int mi = 0; mi < 4; mi++)
#pragma unroll
                for (int ni = 0; ni < 4; ni++)
                    MMA_TF32(acc[mi][ni], af[mi], bfr[ni]);
        }
        buf ^= 1;
    }

    // epilogue: add bias, write
#pragma unroll
    for (int mi = 0; mi < 4; mi++) {
        const int row0 = m0 + wm * 64 + mi * 16 + g;
#pragma unroll
        for (int ni = 0; ni < 4; ni++) {
            const int col = n0 + wn * 32 + ni * 8 + 2 * t;
            float2 bb = *(const float2*)(bias + col);
            float2 v0 = { acc[mi][ni][0] + bb.x, acc[mi][ni][1] + bb.y };
            float2 v1 = { acc[mi][ni][2] + bb.x, acc[mi][ni][3] + bb.y };
            *(float2*)(C + (size_t)row0 * N + col)       = v0;
            *(float2*)(C + (size_t)(row0 + 8) * N + col) = v1;
        }
    }
}

// ---------------- kernel 3: per-head LN + RoPE + layout ----------------
__device__ __forceinline__ float warp_allreduce_sum(float v) {
#pragma unroll
    for (int off = 16; off; off >>= 1) v += __shfl_xor_sync(0xffffffffu, v, off);
    return v;
}

__global__ __launch_bounds__(512) void qk_rope_kernel(
    const float* __restrict__ qkv,
    const float* __restrict__ qsc, const float* __restrict__ ksc,
    float* __restrict__ Qo, float* __restrict__ Ko, float* __restrict__ Vo)
{
    const int bs   = blockIdx.x;          // b*S + s
    const int b    = bs >> 11;            // / 2048
    const int s    = bs & (S_ - 1);
    const int h    = threadIdx.x >> 5;    // warp = head
    const int lane = threadIdx.x & 31;
    const float* base = qkv + (size_t)bs * (3 * D_) + h * HD_;

    float q0 = base[lane],        q1 = base[lane + 32];
    float k0 = base[1024 + lane], k1 = base[1024 + lane + 32];
    float v0 = base[2048 + lane], v1 = base[2048 + lane + 32];

    // LN(q), scale only
    float mu  = warp_allreduce_sum(q0 + q1) * (1.f / 64.f);
    float d0  = q0 - mu, d1 = q1 - mu;
    float var = warp_allreduce_sum(d0*d0 + d1*d1) * (1.f / 64.f);
    float r   = rsqrtf(var + 1e-6f);
    float qn0 = d0 * r * qsc[lane];
    float qn1 = d1 * r * qsc[lane + 32];

    // LN(k)
    mu  = warp_allreduce_sum(k0 + k1) * (1.f / 64.f);
    d0  = k0 - mu; d1 = k1 - mu;
    var = warp_allreduce_sum(d0*d0 + d1*d1) * (1.f / 64.f);
    r   = rsqrtf(var + 1e-6f);
    float kn0 = d0 * r * ksc[lane];
    float kn1 = d1 * r * ksc[lane + 32];

    // RoPE: inv_freq = 10000^(-lane/32); angle = s * inv_freq (fp64 for accuracy)
    double invf = exp(-0.28782313662425575 * (double)lane); // ln(10000)/32
    double ang  = (double)s * invf;
    double sn, cs;
    sincos(ang, &sn, &cs);
    const float c  = (float)cs, si = (float)sn;

    float qr0 = qn0 * c - qn1 * si;
    float qr1 = qn1 * c + qn0 * si;
    float kr0 = kn0 * c - kn1 * si;
    float kr1 = kn1 * c + kn0 * si;

    const size_t o = (((size_t)(b * H_ + h)) * S_ + s) * HD_ + lane;
    Qo[o] = qr0; Qo[o + 32] = qr1;
    Ko[o] = kr0; Ko[o + 32] = kr1;
    Vo[o] = v0;  Vo[o + 32] = v1;
}

// ---------------- kernel 4: flash attention (64q x 64k tiles) ----------------
__global__ __launch_bounds__(256) void attn_kernel(
    const float* __restrict__ Q, const float* __restrict__ K,
    const float* __restrict__ V, float* __restrict__ O)
{
    constexpr int P = 68;  // smem pitch (floats)
    extern __shared__ float sm[];
    float* Qt = sm;                // [d][m] k-major
    float* Kt = sm + 64 * P;       // [d][n] k-major
    float* Vs = sm + 2 * 64 * P;   // [n][d]
    float* Ps = sm + 3 * 64 * P;   // [m][n]

    const int tid = threadIdx.x;
    const int tx = tid & 15, ty = tid >> 4;
    const int bh = blockIdx.y;
    const int q0 = blockIdx.x << 6;
    const float* Qb = Q + ((size_t)bh * S_ + q0) * HD_;
    const float* Kb = K + (size_t)bh * S_ * HD_;
    const float* Vb = V + (size_t)bh * S_ * HD_;

    const int lm  = tid >> 2;        // 0..63 row
    const int ld0 = (tid & 3) << 4;  // 0,16,32,48

    // load Q tile transposed (once)
#pragma unroll
    for (int u = 0; u < 4; ++u) {
        float4 t = *(const float4*)(Qb + (size_t)lm * HD_ + ld0 + (u << 2));
        Qt[(ld0 + (u << 2) + 0) * P + lm] = t.x;
        Qt[(ld0 + (u << 2) + 1) * P + lm] = t.y;
        Qt[(ld0 + (u << 2) + 2) * P + lm] = t.z;
        Qt[(ld0 + (u << 2) + 3) * P + lm] = t.w;
    }

    float m_[4], l_[4], o_[4][4];
#pragma unroll
    for (int i = 0; i < 4; i++) {
        m_[i] = -3.0e38f; l_[i] = 0.f;
#pragma unroll
        for (int j = 0; j < 4; j++) o_[i][j] = 0.f;
    }

    for (int kt = 0; kt < S_; kt += 64) {
        __syncthreads();
#pragma unroll
        for (int u = 0; u < 4; ++u) {
            float4 t = *(const float4*)(Kb + (size_t)(kt + lm) * HD_ + ld0 + (u << 2));
            Kt[(ld0 + (u << 2) + 0) * P + lm] = t.x;
            Kt[(ld0 + (u << 2) + 1) * P + lm] = t.y;
            Kt[(ld0 + (u << 2) + 2) * P + lm] = t.z;
            Kt[(ld0 + (u << 2) + 3) * P + lm] = t.w;
            float4 tv = *(const float4*)(Vb + (size_t)(kt + lm) * HD_ + ld0 + (u << 2));
            *(float4*)(Vs + lm * P + ld0 + (u << 2)) = tv;
        }
        __syncthreads();

        // S = Q K^T (64x64), thread owns 4x4
        float acc[4][4];
#pragma unroll
        for (int i = 0; i < 4; i++)
#pragma unroll
            for (int j = 0; j < 4; j++) acc[i][j] = 0.f;

#pragma unroll 8
        for (int kk = 0; kk < 64; ++kk) {
            float4 a4 = *(const float4*)(Qt + kk * P + (ty << 2));
            float4 b4 = *(const float4*)(Kt + kk * P + (tx << 2));
            float a[4]  = { a4.x, a4.y, a4.z, a4.w };
            float bb[4] = { b4.x, b4.y, b4.z, b4.w };
#pragma unroll
            for (int i = 0; i < 4; i++)
#pragma unroll
                for (int j = 0; j < 4; j++)
                    acc[i][j] = fmaf(a[i], bb[j], acc[i][j]);
        }

        // online softmax (each q row owned by one 16-lane group)
#pragma unroll
        for (int i = 0; i < 4; i++) {
#pragma unroll
            for (int j = 0; j < 4; j++) acc[i][j] *= 0.125f;  // 1/sqrt(64)
            float tm = fmaxf(fmaxf(acc[i][0], acc[i][1]), fmaxf(acc[i][2], acc[i][3]));
#pragma unroll
            for (int off = 1; off < 16; off <<= 1)
                tm = fmaxf(tm, __shfl_xor_sync(0xffffffffu, tm, off, 16));
            float mn = fmaxf(m_[i], tm);
            float al = expf(m_[i] - mn);
            m_[i] = mn;
            float p[4], rs = 0.f;
#pragma unroll
            for (int j = 0; j < 4; j++) { p[j] = expf(acc[i][j] - mn); rs += p[j]; }
#pragma unroll
            for (int off = 1; off < 16; off <<= 1)
                rs += __shfl_xor_sync(0xffffffffu, rs, off, 16);
            l_[i] = l_[i] * al + rs;
#pragma unroll
            for (int j = 0; j < 4; j++) o_[i][j] *= al;
            float4 p4 = { p[0], p[1], p[2], p[3] };
            *(float4*)(Ps + ((ty << 2) + i) * P + (tx << 2)) = p4;
        }
        __syncthreads();

        // O += P V (64x64 x 64x64)
#pragma unroll
        for (int kk = 0; kk < 64; kk += 4) {
            float pr[4][4];
#pragma unroll
            for (int i = 0; i < 4; i++) {
                float4 t = *(const float4*)(Ps + ((ty << 2) + i) * P + kk);
                pr[i][0] = t.x; pr[i][1] = t.y; pr[i][2] = t.z; pr[i][3] = t.w;
            }
#pragma unroll
            for (int u = 0; u < 4; u++) {
                float4 v4 = *(const float4*)(Vs + (kk + u) * P + (tx << 2));
                float vv[4] = { v4.x, v4.y, v4.z, v4.w };
#pragma unroll
                for (int i = 0; i < 4; i++)
#pragma unroll
                    for (int j = 0; j < 4; j++)
                        o_[i][j] = fmaf(pr[i][u], vv[j], o_[i][j]);
            }
        }
    }

    // epilogue: divide by l, write to [b, s, h*64+d]
    const int b = bh >> 4, h = bh & 15;
#pragma unroll
    for (int i = 0; i < 4; i++) {
        float inv = 1.0f / l_[i];
        int row = q0 + (ty << 2) + i;
        float4 o4 = { o_[i][0]*inv, o_[i][1]*inv, o_[i][2]*inv, o_[i][3]*inv };
        *(float4*)(O + ((size_t)(b * S_ + row)) * D_ + h * HD_ + (tx << 2)) = o4;
    }
}

// ---------------- launch ----------------
extern "C" void kernel_launch(void* const* d_in, const int* in_sizes, int n_in,
                              void* d_out, int out_size)
{
    const float* x        = (const float*)d_in[0];
    const float* w_qkv    = (const float*)d_in[1];
    const float* b_qkv    = (const float*)d_in[2];
    const float* w_out    = (const float*)d_in[3];
    const float* b_out    = (const float*)d_in[4];
    const float* ln_scale = (const float*)d_in[5];
    const float* ln_bias  = (const float*)d_in[6];
    const float* q_scale  = (const float*)d_in[7];
    const float* k_scale  = (const float*)d_in[8];
    float* out = (float*)d_out;

    float *xn, *qkv, *q, *k, *v, *attn;
    cudaGetSymbolAddress((void**)&xn,   g_xn);
    cudaGetSymbolAddress((void**)&qkv,  g_qkv);
    cudaGetSymbolAddress((void**)&q,    g_q);
    cudaGetSymbolAddress((void**)&k,    g_k);
    cudaGetSymbolAddress((void**)&v,    g_v);
    cudaGetSymbolAddress((void**)&attn, g_attn);

    const int attn_smem = 4 * 64 * 68 * sizeof(float); // 69632 B
    cudaFuncSetAttribute(attn_kernel, cudaFuncAttributeMaxDynamicSharedMemorySize, attn_smem);

    ln_kernel<<<ROWS_, 256>>>(x, ln_scale, ln_bias, xn);
    tf32_gemm_bias<<<dim3((3 * D_) / 128, ROWS_ / 128), 256>>>(
        xn, w_qkv, b_qkv, qkv, ROWS_, 3 * D_, D_);
    qk_rope_kernel<<<ROWS_, 512>>>(qkv, q_scale, k_scale, q, k, v);
    attn_kernel<<<dim3(S_ / 64, B_ * H_), 256, attn_smem>>>(q, k, v, attn);
    tf32_gemm_bias<<<dim3(D_ / 128, ROWS_ / 128), 256>>>(
        attn, w_out, b_out, out, ROWS_, D_, D_);
}

// round 5
// speedup vs baseline: 2.3650x; 1.7307x over previous
#include <cuda_runtime.h>
#include <cuda_bf16.h>
#include <stdint.h>
#include <math.h>

#define B_  2
#define S_  2048
#define D_  1024
#define H_  16
#define HD_ 64
#define ROWS_ (B_*S_)   // 4096

// ---------------- scratch (device globals; no allocations) ----------------
__device__ float g_xn  [ROWS_*D_];
__device__ float g_qkv [ROWS_*3*D_];
__device__ float g_q   [B_*H_*S_*HD_];
__device__ float g_k   [B_*H_*S_*HD_];
__device__ float g_v   [B_*H_*S_*HD_];
__device__ float g_attn[ROWS_*D_];

// ---------------- kernel 1: LayerNorm over D=1024 ----------------
__global__ __launch_bounds__(256) void ln_kernel(
    const float* __restrict__ x, const float* __restrict__ g,
    const float* __restrict__ b, float* __restrict__ y)
{
    __shared__ float red[16];
    const int row = blockIdx.x, tid = threadIdx.x;
    const float* xr = x + (size_t)row * D_;
    float4 v = *(const float4*)(xr + (tid << 2));
    float s  = v.x + v.y + v.z + v.w;
    float ss = v.x*v.x + v.y*v.y + v.z*v.z + v.w*v.w;
#pragma unroll
    for (int off = 16; off; off >>= 1) {
        s  += __shfl_xor_sync(0xffffffffu, s,  off);
        ss += __shfl_xor_sync(0xffffffffu, ss, off);
    }
    if ((tid & 31) == 0) { red[tid >> 5] = s; red[8 + (tid >> 5)] = ss; }
    __syncthreads();
    if (tid < 8) {
        float a = red[tid], c = red[8 + tid];
#pragma unroll
        for (int off = 4; off; off >>= 1) {
            a += __shfl_xor_sync(0xffu, a, off);
            c += __shfl_xor_sync(0xffu, c, off);
        }
        if (tid == 0) { red[0] = a; red[8] = c; }
    }
    __syncthreads();
    const float mean = red[0] * (1.f / 1024.f);
    const float var  = red[8] * (1.f / 1024.f) - mean * mean;
    const float r    = rsqrtf(var + 1e-6f);
    float4 gv = *(const float4*)(g + (tid << 2));
    float4 bv = *(const float4*)(b + (tid << 2));
    float4 o;
    o.x = (v.x - mean) * r * gv.x + bv.x;
    o.y = (v.y - mean) * r * gv.y + bv.y;
    o.z = (v.z - mean) * r * gv.z + bv.z;
    o.w = (v.w - mean) * r * gv.w + bv.w;
    *(float4*)(y + (size_t)row * D_ + (tid << 2)) = o;
}

// ---------------- tf32 helpers ----------------
__device__ __forceinline__ uint32_t f2tf32(float x) {
    uint32_t r;
    asm("cvt.rna.tf32.f32 %0, %1;" : "=r"(r) : "f"(x));
    return r;
}

#define MMA_TF32(d, a, b)                                              \
    asm volatile("mma.sync.aligned.m16n8k8.row.col.f32.tf32.tf32.f32 " \
        "{%0,%1,%2,%3}, {%4,%5,%6,%7}, {%8,%9}, {%0,%1,%2,%3};"        \
        : "+f"((d)[0]), "+f"((d)[1]), "+f"((d)[2]), "+f"((d)[3])       \
        : "r"((a)[0]), "r"((a)[1]), "r"((a)[2]), "r"((a)[3]),          \
          "r"((b)[0]), "r"((b)[1]))

// ---------------- kernel 2/5: tf32 tensor-core GEMM + bias ----------------
__global__ __launch_bounds__(256) void tf32_gemm_bias(
    const float* __restrict__ A, const float* __restrict__ Bm,
    const float* __restrict__ bias, float* __restrict__ C,
    int M, int N, int K)
{
    constexpr int AP = 20;
    constexpr int BP = 136;
    __shared__ uint32_t As[2][128 * AP];
    __shared__ uint32_t Bs[2][16 * BP];

    const int tid  = threadIdx.x;
    const int wid  = tid >> 5, lane = tid & 31;
    const int g    = lane >> 2, t = lane & 3;
    const int wm   = wid & 1;
    const int wn   = wid >> 1;
    const int m0   = blockIdx.y << 7, n0 = blockIdx.x << 7;

    const int ar = tid >> 1;
    const int ac = (tid & 1) << 3;
    const int br = tid >> 4;
    const int bc = (tid & 15) << 2;

    const float* Ag = A  + (size_t)(m0 + ar) * K + ac;
    const float* Bg = Bm + (size_t)br * N + n0 + bc;

    float acc[4][4][4];
#pragma unroll
    for (int mi = 0; mi < 4; mi++)
#pragma unroll
        for (int ni = 0; ni < 4; ni++)
#pragma unroll
            for (int r = 0; r < 4; r++) acc[mi][ni][r] = 0.f;

    float4 a0v = *(const float4*)(Ag);
    float4 a1v = *(const float4*)(Ag + 4);
    float4 b0v = *(const float4*)(Bg);
    float4 b1v = *(const float4*)(Bg + 64);

    const int KSTEPS = K >> 4;
    int buf = 0;
    for (int ks = 0; ks < KSTEPS; ++ks) {
        {
            uint32_t* p = &As[buf][ar * AP + ac];
            p[0] = f2tf32(a0v.x); p[1] = f2tf32(a0v.y);
            p[2] = f2tf32(a0v.z); p[3] = f2tf32(a0v.w);
            p[4] = f2tf32(a1v.x); p[5] = f2tf32(a1v.y);
            p[6] = f2tf32(a1v.z); p[7] = f2tf32(a1v.w);
            uint32_t* q = &Bs[buf][br * BP + bc];
            q[0]  = f2tf32(b0v.x); q[1]  = f2tf32(b0v.y);
            q[2]  = f2tf32(b0v.z); q[3]  = f2tf32(b0v.w);
            q[64] = f2tf32(b1v.x); q[65] = f2tf32(b1v.y);
            q[66] = f2tf32(b1v.z); q[67] = f2tf32(b1v.w);
        }
        __syncthreads();

        if (ks + 1 < KSTEPS) {
            const float* Ap = Ag + (ks + 1) * 16;
            const float* Bp = Bg + (size_t)(ks + 1) * 16 * N;
            a0v = *(const float4*)(Ap);
            a1v = *(const float4*)(Ap + 4);
            b0v = *(const float4*)(Bp);
            b1v = *(const float4*)(Bp + 64);
        }

#pragma unroll
        for (int kk = 0; kk < 16; kk += 8) {
            uint32_t af[4][4], bfr[4][2];
#pragma unroll
            for (int mi = 0; mi < 4; mi++) {
                const int rb = wm * 64 + mi * 16;
                af[mi][0] = As[buf][(rb + g)     * AP + kk + t];
                af[mi][1] = As[buf][(rb + 8 + g) * AP + kk + t];
                af[mi][2] = As[buf][(rb + g)     * AP + kk + t + 4];
                af[mi][3] = As[buf][(rb + 8 + g) * AP + kk + t + 4];
            }
#pragma unroll
            for (int ni = 0; ni < 4; ni++) {
                const int cb = wn * 32 + ni * 8 + g;
                bfr[ni][0] = Bs[buf][(kk + t)     * BP + cb];
                bfr[ni][1] = Bs[buf][(kk + t + 4) * BP + cb];
            }
#pragma unroll
            for (int mi = 0; mi < 4; mi++)
#pragma unroll
                for (int ni = 0; ni < 4; ni++)
                    MMA_TF32(acc[mi][ni], af[mi], bfr[ni]);
        }
        buf ^= 1;
    }

#pragma unroll
    for (int mi = 0; mi < 4; mi++) {
        const int row0 = m0 + wm * 64 + mi * 16 + g;
#pragma unroll
        for (int ni = 0; ni < 4; ni++) {
            const int col = n0 + wn * 32 + ni * 8 + 2 * t;
            float2 bb = *(const float2*)(bias + col);
            float2 v0 = { acc[mi][ni][0] + bb.x, acc[mi][ni][1] + bb.y };
            float2 v1 = { acc[mi][ni][2] + bb.x, acc[mi][ni][3] + bb.y };
            *(float2*)(C + (size_t)row0 * N + col)       = v0;
            *(float2*)(C + (size_t)(row0 + 8) * N + col) = v1;
        }
    }
}

// ---------------- kernel 3: per-head LN + RoPE + layout ----------------
__device__ __forceinline__ float warp_allreduce_sum(float v) {
#pragma unroll
    for (int off = 16; off; off >>= 1) v += __shfl_xor_sync(0xffffffffu, v, off);
    return v;
}

__global__ __launch_bounds__(512) void qk_rope_kernel(
    const float* __restrict__ qkv,
    const float* __restrict__ qsc, const float* __restrict__ ksc,
    float* __restrict__ Qo, float* __restrict__ Ko, float* __restrict__ Vo)
{
    const int bs   = blockIdx.x;
    const int b    = bs >> 11;
    const int s    = bs & (S_ - 1);
    const int h    = threadIdx.x >> 5;
    const int lane = threadIdx.x & 31;
    const float* base = qkv + (size_t)bs * (3 * D_) + h * HD_;

    float q0 = base[lane],        q1 = base[lane + 32];
    float k0 = base[1024 + lane], k1 = base[1024 + lane + 32];
    float v0 = base[2048 + lane], v1 = base[2048 + lane + 32];

    float mu  = warp_allreduce_sum(q0 + q1) * (1.f / 64.f);
    float d0  = q0 - mu, d1 = q1 - mu;
    float var = warp_allreduce_sum(d0*d0 + d1*d1) * (1.f / 64.f);
    float r   = rsqrtf(var + 1e-6f);
    float qn0 = d0 * r * qsc[lane];
    float qn1 = d1 * r * qsc[lane + 32];

    mu  = warp_allreduce_sum(k0 + k1) * (1.f / 64.f);
    d0  = k0 - mu; d1 = k1 - mu;
    var = warp_allreduce_sum(d0*d0 + d1*d1) * (1.f / 64.f);
    r   = rsqrtf(var + 1e-6f);
    float kn0 = d0 * r * ksc[lane];
    float kn1 = d1 * r * ksc[lane + 32];

    double invf = exp(-0.28782313662425575 * (double)lane);
    double ang  = (double)s * invf;
    double sn, cs;
    sincos(ang, &sn, &cs);
    const float c  = (float)cs, si = (float)sn;

    float qr0 = qn0 * c - qn1 * si;
    float qr1 = qn1 * c + qn0 * si;
    float kr0 = kn0 * c - kn1 * si;
    float kr1 = kn1 * c + kn0 * si;

    const size_t o = (((size_t)(b * H_ + h)) * S_ + s) * HD_ + lane;
    Qo[o] = qr0; Qo[o + 32] = qr1;
    Ko[o] = kr0; Ko[o + 32] = kr1;
    Vo[o] = v0;  Vo[o + 32] = v1;
}

// ---------------- bf16 mma helpers for attention ----------------
#define LDSM_X4(r0,r1,r2,r3,addr)                                          \
    asm volatile("ldmatrix.sync.aligned.m8n8.x4.shared.b16 {%0,%1,%2,%3}, [%4];" \
        : "=r"(r0), "=r"(r1), "=r"(r2), "=r"(r3) : "r"(addr))

#define LDSM_X2(r0,r1,addr)                                                \
    asm volatile("ldmatrix.sync.aligned.m8n8.x2.shared.b16 {%0,%1}, [%2];" \
        : "=r"(r0), "=r"(r1) : "r"(addr))

#define LDSM_X2T(r0,r1,addr)                                               \
    asm volatile("ldmatrix.sync.aligned.m8n8.x2.trans.shared.b16 {%0,%1}, [%2];" \
        : "=r"(r0), "=r"(r1) : "r"(addr))

#define MMA_BF16(d, a0,a1,a2,a3, b0,b1)                                    \
    asm volatile("mma.sync.aligned.m16n8k16.row.col.f32.bf16.bf16.f32 "    \
        "{%0,%1,%2,%3}, {%4,%5,%6,%7}, {%8,%9}, {%0,%1,%2,%3};"            \
        : "+f"((d)[0]), "+f"((d)[1]), "+f"((d)[2]), "+f"((d)[3])           \
        : "r"(a0), "r"(a1), "r"(a2), "r"(a3), "r"(b0), "r"(b1))

__device__ __forceinline__ float ex2f(float x) {
    float y; asm("ex2.approx.f32 %0, %1;" : "=f"(y) : "f"(x)); return y;
}

// pitch for bf16 smem tiles (halfs): 72 -> row stride 144B, ldmatrix conflict-free
#define TP 72
#define TSZ (64 * TP)          // halfs per 64x64 tile

// load 64x64 f32 tile (row stride 64) -> hi/lo bf16 smem tiles, 128 threads
__device__ __forceinline__ void load_conv64(
    const float* __restrict__ gsrc, __nv_bfloat16* hi, __nv_bfloat16* lo, int tid)
{
#pragma unroll
    for (int it = 0; it < 8; ++it) {
        int idx = (tid << 2) + (it << 9);
        int r = idx >> 6, c = idx & 63;
        float4 x = *(const float4*)(gsrc + (size_t)r * HD_ + c);
        __nv_bfloat162 h0 = __floats2bfloat162_rn(x.x, x.y);
        __nv_bfloat162 h1 = __floats2bfloat162_rn(x.z, x.w);
        __nv_bfloat162 l0 = __floats2bfloat162_rn(x.x - __bfloat162float(h0.x),
                                                  x.y - __bfloat162float(h0.y));
        __nv_bfloat162 l1 = __floats2bfloat162_rn(x.z - __bfloat162float(h1.x),
                                                  x.w - __bfloat162float(h1.y));
        *(__nv_bfloat162*)(hi + r * TP + c)     = h0;
        *(__nv_bfloat162*)(hi + r * TP + c + 2) = h1;
        *(__nv_bfloat162*)(lo + r * TP + c)     = l0;
        *(__nv_bfloat162*)(lo + r * TP + c + 2) = l1;
    }
}

// ---------------- kernel 4: tensor-core flash attention (bf16x3) ----------------
__global__ __launch_bounds__(128, 3) void attn_kernel(
    const float* __restrict__ Q, const float* __restrict__ K,
    const float* __restrict__ V, float* __restrict__ O)
{
    extern __shared__ __nv_bfloat16 sh[];
    __nv_bfloat16* Khi = sh;               // also Q staging (hi)
    __nv_bfloat16* Klo = sh + TSZ;         // also Q staging (lo)
    __nv_bfloat16* Vhi = sh + 2 * TSZ;
    __nv_bfloat16* Vlo = sh + 3 * TSZ;

    const int tid  = threadIdx.x;
    const int lane = tid & 31, w = tid >> 5;
    const int g    = lane >> 2, t = lane & 3;
    const int bh   = blockIdx.y;
    const int q0   = blockIdx.x << 6;

    const float* Qb = Q + ((size_t)bh * S_ + q0) * HD_;
    const float* Kb = K + (size_t)bh * S_ * HD_;
    const float* Vb = V + (size_t)bh * S_ * HD_;

    const uint32_t shB  = (uint32_t)__cvta_generic_to_shared(sh);
    const uint32_t KhiB = shB;
    const uint32_t KloB = shB + TSZ * 2;
    const uint32_t VhiB = shB + 2 * TSZ * 2;
    const uint32_t VloB = shB + 3 * TSZ * 2;

    // ---- stage Q (hi/lo) into K region, load A-fragments to registers ----
    load_conv64(Qb, Khi, Klo, tid);
    __syncthreads();

    uint32_t qhf[4][4], qlf[4][4];
    {
        const uint32_t qoff = (((w << 4) + (lane & 15)) * TP + (lane >> 4) * 8) * 2;
#pragma unroll
        for (int kb = 0; kb < 4; ++kb) {
            LDSM_X4(qhf[kb][0], qhf[kb][1], qhf[kb][2], qhf[kb][3], KhiB + qoff + kb * 32);
            LDSM_X4(qlf[kb][0], qlf[kb][1], qlf[kb][2], qlf[kb][3], KloB + qoff + kb * 32);
        }
    }

    const uint32_t kLane = ((lane & 7) * TP + ((lane >> 3) & 1) * 8) * 2;
    const uint32_t vLane = ((lane & 15) * TP) * 2;

    float m0 = -1e30f, m1 = -1e30f, l0 = 0.f, l1 = 0.f;
    float o_[8][4];
#pragma unroll
    for (int nb = 0; nb < 8; nb++)
#pragma unroll
        for (int j = 0; j < 4; j++) o_[nb][j] = 0.f;

    const float SCALE = 0.18033688011112042f;  // log2(e)/8

    for (int kt = 0; kt < S_; kt += 64) {
        __syncthreads();
        load_conv64(Kb + (size_t)kt * HD_, Khi, Klo, tid);
        load_conv64(Vb + (size_t)kt * HD_, Vhi, Vlo, tid);
        __syncthreads();

        // ---- S = Q K^T (warp: 16 x 64), bf16x3 ----
        float S[8][4];
#pragma unroll
        for (int nb = 0; nb < 8; nb++)
#pragma unroll
            for (int j = 0; j < 4; j++) S[nb][j] = 0.f;

#pragma unroll
        for (int nb = 0; nb < 8; ++nb) {
#pragma unroll
            for (int kb = 0; kb < 4; ++kb) {
                const uint32_t off = kLane + (nb * 8 * TP + kb * 16) * 2;
                uint32_t bh0, bh1, bl0, bl1;
                LDSM_X2(bh0, bh1, KhiB + off);
                LDSM_X2(bl0, bl1, KloB + off);
                MMA_BF16(S[nb], qhf[kb][0], qhf[kb][1], qhf[kb][2], qhf[kb][3], bh0, bh1);
                MMA_BF16(S[nb], qhf[kb][0], qhf[kb][1], qhf[kb][2], qhf[kb][3], bl0, bl1);
                MMA_BF16(S[nb], qlf[kb][0], qlf[kb][1], qlf[kb][2], qlf[kb][3], bh0, bh1);
            }
        }

        // ---- online softmax (rows g and g+8; quad-local reductions) ----
        float tm0 = -1e30f, tm1 = -1e30f;
#pragma unroll
        for (int nb = 0; nb < 8; ++nb) {
            S[nb][0] *= SCALE; S[nb][1] *= SCALE;
            S[nb][2] *= SCALE; S[nb][3] *= SCALE;
            tm0 = fmaxf(tm0, fmaxf(S[nb][0], S[nb][1]));
            tm1 = fmaxf(tm1, fmaxf(S[nb][2], S[nb][3]));
        }
        tm0 = fmaxf(tm0, __shfl_xor_sync(0xffffffffu, tm0, 1));
        tm0 = fmaxf(tm0, __shfl_xor_sync(0xffffffffu, tm0, 2));
        tm1 = fmaxf(tm1, __shfl_xor_sync(0xffffffffu, tm1, 1));
        tm1 = fmaxf(tm1, __shfl_xor_sync(0xffffffffu, tm1, 2));

        const float nm0 = fmaxf(m0, tm0), nm1 = fmaxf(m1, tm1);
        const float a0 = ex2f(m0 - nm0),  a1 = ex2f(m1 - nm1);
        m0 = nm0; m1 = nm1;

        float rs0 = 0.f, rs1 = 0.f;
#pragma unroll
        for (int nb = 0; nb < 8; ++nb) {
            S[nb][0] = ex2f(S[nb][0] - m0);
            S[nb][1] = ex2f(S[nb][1] - m0);
            S[nb][2] = ex2f(S[nb][2] - m1);
            S[nb][3] = ex2f(S[nb][3] - m1);
            rs0 += S[nb][0] + S[nb][1];
            rs1 += S[nb][2] + S[nb][3];
        }
        rs0 += __shfl_xor_sync(0xffffffffu, rs0, 1);
        rs0 += __shfl_xor_sync(0xffffffffu, rs0, 2);
        rs1 += __shfl_xor_sync(0xffffffffu, rs1, 1);
        rs1 += __shfl_xor_sync(0xffffffffu, rs1, 2);
        l0 = l0 * a0 + rs0;
        l1 = l1 * a1 + rs1;
#pragma unroll
        for (int nb = 0; nb < 8; ++nb) {
            o_[nb][0] *= a0; o_[nb][1] *= a0;
            o_[nb][2] *= a1; o_[nb][3] *= a1;
        }

        // ---- O += P V  (bf16x3; P from register fragments) ----
#pragma unroll
        for (int kb = 0; kb < 4; ++kb) {
            uint32_t phi[4], plo[4];
#pragma unroll
            for (int half = 0; half < 2; ++half) {
                const float c0 = S[2 * kb + half][0], c1 = S[2 * kb + half][1];
                const float c2 = S[2 * kb + half][2], c3 = S[2 * kb + half][3];
                __nv_bfloat162 h0 = __floats2bfloat162_rn(c0, c1);
                __nv_bfloat162 h1 = __floats2bfloat162_rn(c2, c3);
                __nv_bfloat162 e0 = __floats2bfloat162_rn(c0 - __bfloat162float(h0.x),
                                                          c1 - __bfloat162float(h0.y));
                __nv_bfloat162 e1 = __floats2bfloat162_rn(c2 - __bfloat162float(h1.x),
                                                          c3 - __bfloat162float(h1.y));
                phi[2 * half]     = *(uint32_t*)&h0;
                phi[2 * half + 1] = *(uint32_t*)&h1;
                plo[2 * half]     = *(uint32_t*)&e0;
                plo[2 * half + 1] = *(uint32_t*)&e1;
            }
#pragma unroll
            for (int nb = 0; nb < 8; ++nb) {
                const uint32_t off = vLane + (kb * 16 * TP + nb * 8) * 2;
                uint32_t vh0, vh1, vl0, vl1;
                LDSM_X2T(vh0, vh1, VhiB + off);
                LDSM_X2T(vl0, vl1, VloB + off);
                MMA_BF16(o_[nb], phi[0], phi[1], phi[2], phi[3], vh0, vh1);
                MMA_BF16(o_[nb], phi[0], phi[1], phi[2], phi[3], vl0, vl1);
                MMA_BF16(o_[nb], plo[0], plo[1], plo[2], plo[3], vh0, vh1);
            }
        }
    }

    // ---- epilogue: O /= l, write [b, s, h*64+d] ----
    const int b = bh >> 4, h = bh & 15;
    const float inv0 = 1.f / l0, inv1 = 1.f / l1;
    const int row0 = q0 + (w << 4) + g;
#pragma unroll
    for (int nb = 0; nb < 8; ++nb) {
        const int col = h * HD_ + nb * 8 + 2 * t;
        float2 v0 = { o_[nb][0] * inv0, o_[nb][1] * inv0 };
        float2 v1 = { o_[nb][2] * inv1, o_[nb][3] * inv1 };
        *(float2*)(O + (size_t)(b * S_ + row0) * D_ + col)     = v0;
        *(float2*)(O + (size_t)(b * S_ + row0 + 8) * D_ + col) = v1;
    }
}

// ---------------- launch ----------------
extern "C" void kernel_launch(void* const* d_in, const int* in_sizes, int n_in,
                              void* d_out, int out_size)
{
    const float* x        = (const float*)d_in[0];
    const float* w_qkv    = (const float*)d_in[1];
    const float* b_qkv    = (const float*)d_in[2];
    const float* w_out    = (const float*)d_in[3];
    const float* b_out    = (const float*)d_in[4];
    const float* ln_scale = (const float*)d_in[5];
    const float* ln_bias  = (const float*)d_in[6];
    const float* q_scale  = (const float*)d_in[7];
    const float* k_scale  = (const float*)d_in[8];
    float* out = (float*)d_out;

    float *xn, *qkv, *q, *k, *v, *attn;
    cudaGetSymbolAddress((void**)&xn,   g_xn);
    cudaGetSymbolAddress((void**)&qkv,  g_qkv);
    cudaGetSymbolAddress((void**)&q,    g_q);
    cudaGetSymbolAddress((void**)&k,    g_k);
    cudaGetSymbolAddress((void**)&v,    g_v);
    cudaGetSymbolAddress((void**)&attn, g_attn);

    const int attn_smem = 4 * TSZ * sizeof(__nv_bfloat16); // 36864 B

    ln_kernel<<<ROWS_, 256>>>(x, ln_scale, ln_bias, xn);
    tf32_gemm_bias<<<dim3((3 * D_) / 128, ROWS_ / 128), 256>>>(
        xn, w_qkv, b_qkv, qkv, ROWS_, 3 * D_, D_);
    qk_rope_kernel<<<ROWS_, 512>>>(qkv, q_scale, k_scale, q, k, v);
    attn_kernel<<<dim3(S_ / 64, B_ * H_), 128, attn_smem>>>(q, k, v, attn);
    tf32_gemm_bias<<<dim3(D_ / 128, ROWS_ / 128), 256>>>(
        attn, w_out, b_out, out, ROWS_, D_, D_);
}

// round 6
// speedup vs baseline: 2.5446x; 1.0759x over previous
#include <cuda_runtime.h>
#include <cuda_bf16.h>
#include <stdint.h>
#include <math.h>

#define B_  2
#define S_  2048
#define D_  1024
#define H_  16
#define HD_ 64
#define ROWS_ (B_*S_)   // 4096

// ---------------- scratch (device globals; no allocations) ----------------
__device__ float g_xn  [ROWS_*D_];
__device__ float g_qkv [ROWS_*3*D_];
__device__ float g_attn[ROWS_*D_];
__device__ __nv_bfloat16 g_qh[B_*H_*S_*HD_];
__device__ __nv_bfloat16 g_ql[B_*H_*S_*HD_];
__device__ __nv_bfloat16 g_kh[B_*H_*S_*HD_];
__device__ __nv_bfloat16 g_kl[B_*H_*S_*HD_];
__device__ __nv_bfloat16 g_vh[B_*H_*S_*HD_];
__device__ __nv_bfloat16 g_vl[B_*H_*S_*HD_];

// ---------------- kernel 1: LayerNorm over D=1024 ----------------
__global__ __launch_bounds__(256) void ln_kernel(
    const float* __restrict__ x, const float* __restrict__ g,
    const float* __restrict__ b, float* __restrict__ y)
{
    __shared__ float red[16];
    const int row = blockIdx.x, tid = threadIdx.x;
    const float* xr = x + (size_t)row * D_;
    float4 v = *(const float4*)(xr + (tid << 2));
    float s  = v.x + v.y + v.z + v.w;
    float ss = v.x*v.x + v.y*v.y + v.z*v.z + v.w*v.w;
#pragma unroll
    for (int off = 16; off; off >>= 1) {
        s  += __shfl_xor_sync(0xffffffffu, s,  off);
        ss += __shfl_xor_sync(0xffffffffu, ss, off);
    }
    if ((tid & 31) == 0) { red[tid >> 5] = s; red[8 + (tid >> 5)] = ss; }
    __syncthreads();
    if (tid < 8) {
        float a = red[tid], c = red[8 + tid];
#pragma unroll
        for (int off = 4; off; off >>= 1) {
            a += __shfl_xor_sync(0xffu, a, off);
            c += __shfl_xor_sync(0xffu, c, off);
        }
        if (tid == 0) { red[0] = a; red[8] = c; }
    }
    __syncthreads();
    const float mean = red[0] * (1.f / 1024.f);
    const float var  = red[8] * (1.f / 1024.f) - mean * mean;
    const float r    = rsqrtf(var + 1e-6f);
    float4 gv = *(const float4*)(g + (tid << 2));
    float4 bv = *(const float4*)(b + (tid << 2));
    float4 o;
    o.x = (v.x - mean) * r * gv.x + bv.x;
    o.y = (v.y - mean) * r * gv.y + bv.y;
    o.z = (v.z - mean) * r * gv.z + bv.z;
    o.w = (v.w - mean) * r * gv.w + bv.w;
    *(float4*)(y + (size_t)row * D_ + (tid << 2)) = o;
}

// ---------------- tf32 helpers ----------------
__device__ __forceinline__ uint32_t f2tf32(float x) {
    uint32_t r;
    asm("cvt.rna.tf32.f32 %0, %1;" : "=r"(r) : "f"(x));
    return r;
}

#define MMA_TF32(d, a, b)                                              \
    asm volatile("mma.sync.aligned.m16n8k8.row.col.f32.tf32.tf32.f32 " \
        "{%0,%1,%2,%3}, {%4,%5,%6,%7}, {%8,%9}, {%0,%1,%2,%3};"        \
        : "+f"((d)[0]), "+f"((d)[1]), "+f"((d)[2]), "+f"((d)[3])       \
        : "r"((a)[0]), "r"((a)[1]), "r"((a)[2]), "r"((a)[3]),          \
          "r"((b)[0]), "r"((b)[1]))

// ---------------- kernel 2/5: tf32 tensor-core GEMM + bias ----------------
__global__ __launch_bounds__(256) void tf32_gemm_bias(
    const float* __restrict__ A, const float* __restrict__ Bm,
    const float* __restrict__ bias, float* __restrict__ C,
    int M, int N, int K)
{
    constexpr int AP = 20;
    constexpr int BP = 136;
    __shared__ uint32_t As[2][128 * AP];
    __shared__ uint32_t Bs[2][16 * BP];

    const int tid  = threadIdx.x;
    const int wid  = tid >> 5, lane = tid & 31;
    const int g    = lane >> 2, t = lane & 3;
    const int wm   = wid & 1;
    const int wn   = wid >> 1;
    const int m0   = blockIdx.y << 7, n0 = blockIdx.x << 7;

    const int ar = tid >> 1;
    const int ac = (tid & 1) << 3;
    const int br = tid >> 4;
    const int bc = (tid & 15) << 2;

    const float* Ag = A  + (size_t)(m0 + ar) * K + ac;
    const float* Bg = Bm + (size_t)br * N + n0 + bc;

    float acc[4][4][4];
#pragma unroll
    for (int mi = 0; mi < 4; mi++)
#pragma unroll
        for (int ni = 0; ni < 4; ni++)
#pragma unroll
            for (int r = 0; r < 4; r++) acc[mi][ni][r] = 0.f;

    float4 a0v = *(const float4*)(Ag);
    float4 a1v = *(const float4*)(Ag + 4);
    float4 b0v = *(const float4*)(Bg);
    float4 b1v = *(const float4*)(Bg + 64);

    const int KSTEPS = K >> 4;
    int buf = 0;
    for (int ks = 0; ks < KSTEPS; ++ks) {
        {
            uint32_t* p = &As[buf][ar * AP + ac];
            p[0] = f2tf32(a0v.x); p[1] = f2tf32(a0v.y);
            p[2] = f2tf32(a0v.z); p[3] = f2tf32(a0v.w);
            p[4] = f2tf32(a1v.x); p[5] = f2tf32(a1v.y);
            p[6] = f2tf32(a1v.z); p[7] = f2tf32(a1v.w);
            uint32_t* q = &Bs[buf][br * BP + bc];
            q[0]  = f2tf32(b0v.x); q[1]  = f2tf32(b0v.y);
            q[2]  = f2tf32(b0v.z); q[3]  = f2tf32(b0v.w);
            q[64] = f2tf32(b1v.x); q[65] = f2tf32(b1v.y);
            q[66] = f2tf32(b1v.z); q[67] = f2tf32(b1v.w);
        }
        __syncthreads();

        if (ks + 1 < KSTEPS) {
            const float* Ap = Ag + (ks + 1) * 16;
            const float* Bp = Bg + (size_t)(ks + 1) * 16 * N;
            a0v = *(const float4*)(Ap);
            a1v = *(const float4*)(Ap + 4);
            b0v = *(const float4*)(Bp);
            b1v = *(const float4*)(Bp + 64);
        }

#pragma unroll
        for (int kk = 0; kk < 16; kk += 8) {
            uint32_t af[4][4], bfr[4][2];
#pragma unroll
            for (int mi = 0; mi < 4; mi++) {
                const int rb = wm * 64 + mi * 16;
                af[mi][0] = As[buf][(rb + g)     * AP + kk + t];
                af[mi][1] = As[buf][(rb + 8 + g) * AP + kk + t];
                af[mi][2] = As[buf][(rb + g)     * AP + kk + t + 4];
                af[mi][3] = As[buf][(rb + 8 + g) * AP + kk + t + 4];
            }
#pragma unroll
            for (int ni = 0; ni < 4; ni++) {
                const int cb = wn * 32 + ni * 8 + g;
                bfr[ni][0] = Bs[buf][(kk + t)     * BP + cb];
                bfr[ni][1] = Bs[buf][(kk + t + 4) * BP + cb];
            }
#pragma unroll
            for (int mi = 0; mi < 4; mi++)
#pragma unroll
                for (int ni = 0; ni < 4; ni++)
                    MMA_TF32(acc[mi][ni], af[mi], bfr[ni]);
        }
        buf ^= 1;
    }

#pragma unroll
    for (int mi = 0; mi < 4; mi++) {
        const int row0 = m0 + wm * 64 + mi * 16 + g;
#pragma unroll
        for (int ni = 0; ni < 4; ni++) {
            const int col = n0 + wn * 32 + ni * 8 + 2 * t;
            float2 bb = *(const float2*)(bias + col);
            float2 v0 = { acc[mi][ni][0] + bb.x, acc[mi][ni][1] + bb.y };
            float2 v1 = { acc[mi][ni][2] + bb.x, acc[mi][ni][3] + bb.y };
            *(float2*)(C + (size_t)row0 * N + col)       = v0;
            *(float2*)(C + (size_t)(row0 + 8) * N + col) = v1;
        }
    }
}

// ---------------- kernel 3: per-head LN + RoPE -> bf16 hi/lo ----------------
__device__ __forceinline__ float warp_allreduce_sum(float v) {
#pragma unroll
    for (int off = 16; off; off >>= 1) v += __shfl_xor_sync(0xffffffffu, v, off);
    return v;
}

__device__ __forceinline__ void split_store(
    __nv_bfloat16* hi, __nv_bfloat16* lo, size_t idx, float x)
{
    __nv_bfloat16 h = __float2bfloat16_rn(x);
    hi[idx] = h;
    lo[idx] = __float2bfloat16_rn(x - __bfloat162float(h));
}

__global__ __launch_bounds__(512) void qk_rope_kernel(
    const float* __restrict__ qkv,
    const float* __restrict__ qsc, const float* __restrict__ ksc,
    __nv_bfloat16* __restrict__ Qh, __nv_bfloat16* __restrict__ Ql,
    __nv_bfloat16* __restrict__ Kh, __nv_bfloat16* __restrict__ Kl,
    __nv_bfloat16* __restrict__ Vh, __nv_bfloat16* __restrict__ Vl)
{
    const int bs   = blockIdx.x;
    const int b    = bs >> 11;
    const int s    = bs & (S_ - 1);
    const int h    = threadIdx.x >> 5;
    const int lane = threadIdx.x & 31;
    const float* base = qkv + (size_t)bs * (3 * D_) + h * HD_;

    float q0 = base[lane],        q1 = base[lane + 32];
    float k0 = base[1024 + lane], k1 = base[1024 + lane + 32];
    float v0 = base[2048 + lane], v1 = base[2048 + lane + 32];

    float mu  = warp_allreduce_sum(q0 + q1) * (1.f / 64.f);
    float d0  = q0 - mu, d1 = q1 - mu;
    float var = warp_allreduce_sum(d0*d0 + d1*d1) * (1.f / 64.f);
    float r   = rsqrtf(var + 1e-6f);
    float qn0 = d0 * r * qsc[lane];
    float qn1 = d1 * r * qsc[lane + 32];

    mu  = warp_allreduce_sum(k0 + k1) * (1.f / 64.f);
    d0  = k0 - mu; d1 = k1 - mu;
    var = warp_allreduce_sum(d0*d0 + d1*d1) * (1.f / 64.f);
    r   = rsqrtf(var + 1e-6f);
    float kn0 = d0 * r * ksc[lane];
    float kn1 = d1 * r * ksc[lane + 32];

    double invf = exp(-0.28782313662425575 * (double)lane);
    double ang  = (double)s * invf;
    double sn, cs;
    sincos(ang, &sn, &cs);
    const float c  = (float)cs, si = (float)sn;

    float qr0 = qn0 * c - qn1 * si;
    float qr1 = qn1 * c + qn0 * si;
    float kr0 = kn0 * c - kn1 * si;
    float kr1 = kn1 * c + kn0 * si;

    const size_t o = (((size_t)(b * H_ + h)) * S_ + s) * HD_ + lane;
    split_store(Qh, Ql, o,      qr0);
    split_store(Qh, Ql, o + 32, qr1);
    split_store(Kh, Kl, o,      kr0);
    split_store(Kh, Kl, o + 32, kr1);
    split_store(Vh, Vl, o,      v0);
    split_store(Vh, Vl, o + 32, v1);
}

// ---------------- bf16 mma helpers for attention ----------------
#define LDSM_X2(r0,r1,addr)                                                \
    asm volatile("ldmatrix.sync.aligned.m8n8.x2.shared.b16 {%0,%1}, [%2];" \
        : "=r"(r0), "=r"(r1) : "r"(addr))

#define LDSM_X2T(r0,r1,addr)                                               \
    asm volatile("ldmatrix.sync.aligned.m8n8.x2.trans.shared.b16 {%0,%1}, [%2];" \
        : "=r"(r0), "=r"(r1) : "r"(addr))

#define MMA_BF16(d, a0,a1,a2,a3, b0,b1)                                    \
    asm volatile("mma.sync.aligned.m16n8k16.row.col.f32.bf16.bf16.f32 "    \
        "{%0,%1,%2,%3}, {%4,%5,%6,%7}, {%8,%9}, {%0,%1,%2,%3};"            \
        : "+f"((d)[0]), "+f"((d)[1]), "+f"((d)[2]), "+f"((d)[3])           \
        : "r"(a0), "r"(a1), "r"(a2), "r"(a3), "r"(b0), "r"(b1))

#define CP16(dst, src)                                                     \
    asm volatile("cp.async.ca.shared.global [%0], [%1], 16;"               \
        :: "r"(dst), "l"(src))

#define CP_COMMIT()  asm volatile("cp.async.commit_group;")
#define CP_WAIT(n)   asm volatile("cp.async.wait_group %0;" :: "n"(n))

__device__ __forceinline__ float ex2f(float x) {
    float y; asm("ex2.approx.f32 %0, %1;" : "=f"(y) : "f"(x)); return y;
}

// pitch for bf16 smem tiles (halfs): 72 -> row stride 144B, ldmatrix conflict-free
#define TP 72
#define TSZ (64 * TP)          // halfs per 64x64 tile

// cp.async a 64x64 bf16 tile (gmem row stride 64) into smem pitch-72 tile
__device__ __forceinline__ void cp_tile(
    uint32_t dst, const __nv_bfloat16* __restrict__ src, int tid)
{
#pragma unroll
    for (int it = 0; it < 4; ++it) {
        int c = tid + (it << 7);       // 0..511 chunks of 16B
        int r = c >> 3, cc = c & 7;
        CP16(dst + r * (TP * 2) + cc * 16, src + r * HD_ + cc * 8);
    }
}

// ---------------- kernel 4: tensor-core flash attention (bf16x3, cp.async) ----
__global__ __launch_bounds__(128, 3) void attn_kernel(
    const __nv_bfloat16* __restrict__ Qh, const __nv_bfloat16* __restrict__ Ql,
    const __nv_bfloat16* __restrict__ Kh, const __nv_bfloat16* __restrict__ Kl,
    const __nv_bfloat16* __restrict__ Vh, const __nv_bfloat16* __restrict__ Vl,
    float* __restrict__ O)
{
    extern __shared__ __nv_bfloat16 sh[];   // [2 stages][4 tiles][TSZ]

    const int tid  = threadIdx.x;
    const int lane = tid & 31, w = tid >> 5;
    const int g    = lane >> 2, t = lane & 3;
    const int bh   = blockIdx.y;
    const int q0   = blockIdx.x << 6;

    const __nv_bfloat16* Kbh = Kh + (size_t)bh * S_ * HD_;
    const __nv_bfloat16* Kbl = Kl + (size_t)bh * S_ * HD_;
    const __nv_bfloat16* Vbh = Vh + (size_t)bh * S_ * HD_;
    const __nv_bfloat16* Vbl = Vl + (size_t)bh * S_ * HD_;

    const uint32_t shB = (uint32_t)__cvta_generic_to_shared(sh);

    // ---- Q A-fragments straight from gmem (once) ----
    uint32_t qhf[4][4], qlf[4][4];
    {
        const __nv_bfloat16* Qbase = Qh + ((size_t)bh * S_ + q0 + (w << 4)) * HD_;
        const __nv_bfloat16* Qbl   = Ql + ((size_t)bh * S_ + q0 + (w << 4)) * HD_;
#pragma unroll
        for (int kb = 0; kb < 4; ++kb) {
            const int c0 = kb * 16 + 2 * t;
            qhf[kb][0] = *(const uint32_t*)(Qbase + (size_t)g       * HD_ + c0);
            qhf[kb][1] = *(const uint32_t*)(Qbase + (size_t)(g + 8) * HD_ + c0);
            qhf[kb][2] = *(const uint32_t*)(Qbase + (size_t)g       * HD_ + c0 + 8);
            qhf[kb][3] = *(const uint32_t*)(Qbase + (size_t)(g + 8) * HD_ + c0 + 8);
            qlf[kb][0] = *(const uint32_t*)(Qbl   + (size_t)g       * HD_ + c0);
            qlf[kb][1] = *(const uint32_t*)(Qbl   + (size_t)(g + 8) * HD_ + c0);
            qlf[kb][2] = *(const uint32_t*)(Qbl   + (size_t)g       * HD_ + c0 + 8);
            qlf[kb][3] = *(const uint32_t*)(Qbl   + (size_t)(g + 8) * HD_ + c0 + 8);
        }
    }

    const uint32_t kLane = ((lane & 7) * TP + ((lane >> 3) & 1) * 8) * 2;
    const uint32_t vLane = ((lane & 15) * TP) * 2;

    float m0 = -1e30f, m1 = -1e30f, l0 = 0.f, l1 = 0.f;
    float o_[8][4];
#pragma unroll
    for (int nb = 0; nb < 8; nb++)
#pragma unroll
        for (int j = 0; j < 4; j++) o_[nb][j] = 0.f;

    const float SCALE = 0.18033688011112042f;  // log2(e)/8

    // ---- prologue: stage 0 loads ----
    {
        const uint32_t st0 = shB;
        cp_tile(st0,                Kbh, tid);
        cp_tile(st0 + TSZ * 2,      Kbl, tid);
        cp_tile(st0 + 2 * TSZ * 2,  Vbh, tid);
        cp_tile(st0 + 3 * TSZ * 2,  Vbl, tid);
        CP_COMMIT();
    }

    int buf = 0;
    for (int kt = 0; kt < S_; kt += 64) {
        if (kt + 64 < S_) {
            const uint32_t stn = shB + (buf ^ 1) * 4 * TSZ * 2;
            const size_t goff = (size_t)(kt + 64) * HD_;
            cp_tile(stn,               Kbh + goff, tid);
            cp_tile(stn + TSZ * 2,     Kbl + goff, tid);
            cp_tile(stn + 2 * TSZ * 2, Vbh + goff, tid);
            cp_tile(stn + 3 * TSZ * 2, Vbl + goff, tid);
            CP_COMMIT();
            CP_WAIT(1);
        } else {
            CP_WAIT(0);
        }
        __syncthreads();

        const uint32_t KhiB = shB + buf * 4 * TSZ * 2;
        const uint32_t KloB = KhiB + TSZ * 2;
        const uint32_t VhiB = KhiB + 2 * TSZ * 2;
        const uint32_t VloB = KhiB + 3 * TSZ * 2;

        // ---- S = Q K^T (warp: 16 x 64), bf16x3 ----
        float S[8][4];
#pragma unroll
        for (int nb = 0; nb < 8; nb++)
#pragma unroll
            for (int j = 0; j < 4; j++) S[nb][j] = 0.f;

#pragma unroll
        for (int nb = 0; nb < 8; ++nb) {
#pragma unroll
            for (int kb = 0; kb < 4; ++kb) {
                const uint32_t off = kLane + (nb * 8 * TP + kb * 16) * 2;
                uint32_t bh0, bh1, bl0, bl1;
                LDSM_X2(bh0, bh1, KhiB + off);
                LDSM_X2(bl0, bl1, KloB + off);
                MMA_BF16(S[nb], qhf[kb][0], qhf[kb][1], qhf[kb][2], qhf[kb][3], bh0, bh1);
                MMA_BF16(S[nb], qhf[kb][0], qhf[kb][1], qhf[kb][2], qhf[kb][3], bl0, bl1);
                MMA_BF16(S[nb], qlf[kb][0], qlf[kb][1], qlf[kb][2], qlf[kb][3], bh0, bh1);
            }
        }

        // ---- online softmax ----
        float tm0 = -1e30f, tm1 = -1e30f;
#pragma unroll
        for (int nb = 0; nb < 8; ++nb) {
            S[nb][0] *= SCALE; S[nb][1] *= SCALE;
            S[nb][2] *= SCALE; S[nb][3] *= SCALE;
            tm0 = fmaxf(tm0, fmaxf(S[nb][0], S[nb][1]));
            tm1 = fmaxf(tm1, fmaxf(S[nb][2], S[nb][3]));
        }
        tm0 = fmaxf(tm0, __shfl_xor_sync(0xffffffffu, tm0, 1));
        tm0 = fmaxf(tm0, __shfl_xor_sync(0xffffffffu, tm0, 2));
        tm1 = fmaxf(tm1, __shfl_xor_sync(0xffffffffu, tm1, 1));
        tm1 = fmaxf(tm1, __shfl_xor_sync(0xffffffffu, tm1, 2));

        const float nm0 = fmaxf(m0, tm0), nm1 = fmaxf(m1, tm1);
        const float a0 = ex2f(m0 - nm0),  a1 = ex2f(m1 - nm1);
        m0 = nm0; m1 = nm1;

        float rs0 = 0.f, rs1 = 0.f;
#pragma unroll
        for (int nb = 0; nb < 8; ++nb) {
            S[nb][0] = ex2f(S[nb][0] - m0);
            S[nb][1] = ex2f(S[nb][1] - m0);
            S[nb][2] = ex2f(S[nb][2] - m1);
            S[nb][3] = ex2f(S[nb][3] - m1);
            rs0 += S[nb][0] + S[nb][1];
            rs1 += S[nb][2] + S[nb][3];
        }
        rs0 += __shfl_xor_sync(0xffffffffu, rs0, 1);
        rs0 += __shfl_xor_sync(0xffffffffu, rs0, 2);
        rs1 += __shfl_xor_sync(0xffffffffu, rs1, 1);
        rs1 += __shfl_xor_sync(0xffffffffu, rs1, 2);
        l0 = l0 * a0 + rs0;
        l1 = l1 * a1 + rs1;
#pragma unroll
        for (int nb = 0; nb < 8; ++nb) {
            o_[nb][0] *= a0; o_[nb][1] *= a0;
            o_[nb][2] *= a1; o_[nb][3] *= a1;
        }

        // ---- O += P V  (bf16x3; P from register fragments) ----
#pragma unroll
        for (int kb = 0; kb < 4; ++kb) {
            uint32_t phi[4], plo[4];
#pragma unroll
            for (int half = 0; half < 2; ++half) {
                const float c0 = S[2 * kb + half][0], c1 = S[2 * kb + half][1];
                const float c2 = S[2 * kb + half][2], c3 = S[2 * kb + half][3];
                __nv_bfloat162 h0 = __floats2bfloat162_rn(c0, c1);
                __nv_bfloat162 h1 = __floats2bfloat162_rn(c2, c3);
                __nv_bfloat162 e0 = __floats2bfloat162_rn(c0 - __bfloat162float(h0.x),
                                                          c1 - __bfloat162float(h0.y));
                __nv_bfloat162 e1 = __floats2bfloat162_rn(c2 - __bfloat162float(h1.x),
                                                          c3 - __bfloat162float(h1.y));
                phi[2 * half]     = *(uint32_t*)&h0;
                phi[2 * half + 1] = *(uint32_t*)&h1;
                plo[2 * half]     = *(uint32_t*)&e0;
                plo[2 * half + 1] = *(uint32_t*)&e1;
            }
#pragma unroll
            for (int nb = 0; nb < 8; ++nb) {
                const uint32_t off = vLane + (kb * 16 * TP + nb * 8) * 2;
                uint32_t vh0, vh1, vl0, vl1;
                LDSM_X2T(vh0, vh1, VhiB + off);
                LDSM_X2T(vl0, vl1, VloB + off);
                MMA_BF16(o_[nb], phi[0], phi[1], phi[2], phi[3], vh0, vh1);
                MMA_BF16(o_[nb], phi[0], phi[1], phi[2], phi[3], vl0, vl1);
                MMA_BF16(o_[nb], plo[0], plo[1], plo[2], plo[3], vh0, vh1);
            }
        }
        __syncthreads();   // all warps done with buf before it is refilled
        buf ^= 1;
    }

    // ---- epilogue: O /= l, write [b, s, h*64+d] ----
    const int b = bh >> 4, h = bh & 15;
    const float inv0 = 1.f / l0, inv1 = 1.f / l1;
    const int row0 = q0 + (w << 4) + g;
#pragma unroll
    for (int nb = 0; nb < 8; ++nb) {
        const int col = h * HD_ + nb * 8 + 2 * t;
        float2 v0 = { o_[nb][0] * inv0, o_[nb][1] * inv0 };
        float2 v1 = { o_[nb][2] * inv1, o_[nb][3] * inv1 };
        *(float2*)(O + (size_t)(b * S_ + row0) * D_ + col)     = v0;
        *(float2*)(O + (size_t)(b * S_ + row0 + 8) * D_ + col) = v1;
    }
}

// ---------------- launch ----------------
extern "C" void kernel_launch(void* const* d_in, const int* in_sizes, int n_in,
                              void* d_out, int out_size)
{
    const float* x        = (const float*)d_in[0];
    const float* w_qkv    = (const float*)d_in[1];
    const float* b_qkv    = (const float*)d_in[2];
    const float* w_out    = (const float*)d_in[3];
    const float* b_out    = (const float*)d_in[4];
    const float* ln_scale = (const float*)d_in[5];
    const float* ln_bias  = (const float*)d_in[6];
    const float* q_scale  = (const float*)d_in[7];
    const float* k_scale  = (const float*)d_in[8];
    float* out = (float*)d_out;

    float *xn, *qkv, *attn;
    __nv_bfloat16 *qh, *ql, *kh, *kl, *vh, *vl;
    cudaGetSymbolAddress((void**)&xn,   g_xn);
    cudaGetSymbolAddress((void**)&qkv,  g_qkv);
    cudaGetSymbolAddress((void**)&attn, g_attn);
    cudaGetSymbolAddress((void**)&qh,   g_qh);
    cudaGetSymbolAddress((void**)&ql,   g_ql);
    cudaGetSymbolAddress((void**)&kh,   g_kh);
    cudaGetSymbolAddress((void**)&kl,   g_kl);
    cudaGetSymbolAddress((void**)&vh,   g_vh);
    cudaGetSymbolAddress((void**)&vl,   g_vl);

    const int attn_smem = 2 * 4 * TSZ * sizeof(__nv_bfloat16); // 73728 B
    cudaFuncSetAttribute(attn_kernel, cudaFuncAttributeMaxDynamicSharedMemorySize, attn_smem);

    ln_kernel<<<ROWS_, 256>>>(x, ln_scale, ln_bias, xn);
    tf32_gemm_bias<<<dim3((3 * D_) / 128, ROWS_ / 128), 256>>>(
        xn, w_qkv, b_qkv, qkv, ROWS_, 3 * D_, D_);
    qk_rope_kernel<<<ROWS_, 512>>>(qkv, q_scale, k_scale, qh, ql, kh, kl, vh, vl);
    attn_kernel<<<dim3(S_ / 64, B_ * H_), 128, attn_smem>>>(qh, ql, kh, kl, vh, vl, attn);
    tf32_gemm_bias<<<dim3(D_ / 128, ROWS_ / 128), 256>>>(
        attn, w_out, b_out, out, ROWS_, D_, D_);
}

// round 8
// speedup vs baseline: 3.6091x; 1.4183x over previous
#include <cuda_runtime.h>
#include <cuda_bf16.h>
#include <stdint.h>
#include <math.h>

#define B_  2
#define S_  2048
#define D_  1024
#define H_  16
#define HD_ 64
#define ROWS_ (B_*S_)   // 4096

// ---------------- scratch (device globals; no allocations) ----------------
__device__ float g_xn  [ROWS_*D_];
__device__ float g_qkv [ROWS_*3*D_];
__device__ float g_attn[ROWS_*D_];
__device__ float g_wqt [D_*3*D_];     // tf32-rounded w_qkv
__device__ float g_wot [D_*D_];       // tf32-rounded w_out
__device__ float2 g_rtab[S_*32];      // RoPE cos/sin table
__device__ __nv_bfloat16 g_qh[B_*H_*S_*HD_];
__device__ __nv_bfloat16 g_ql[B_*H_*S_*HD_];
__device__ __nv_bfloat16 g_kh[B_*H_*S_*HD_];
__device__ __nv_bfloat16 g_kl[B_*H_*S_*HD_];
__device__ __nv_bfloat16 g_vh[B_*H_*S_*HD_];
__device__ __nv_bfloat16 g_vl[B_*H_*S_*HD_];

// ---------------- helpers ----------------
__device__ __forceinline__ uint32_t f2tf32(float x) {
    uint32_t r;
    asm("cvt.rna.tf32.f32 %0, %1;" : "=r"(r) : "f"(x));
    return r;
}
__device__ __forceinline__ float rnd_tf32(float x) {
    return __uint_as_float(f2tf32(x));
}

#define MMA_TF32(d, a, b)                                              \
    asm volatile("mma.sync.aligned.m16n8k8.row.col.f32.tf32.tf32.f32 " \
        "{%0,%1,%2,%3}, {%4,%5,%6,%7}, {%8,%9}, {%0,%1,%2,%3};"        \
        : "+f"((d)[0]), "+f"((d)[1]), "+f"((d)[2]), "+f"((d)[3])       \
        : "r"((a)[0]), "r"((a)[1]), "r"((a)[2]), "r"((a)[3]),          \
          "r"((b)[0]), "r"((b)[1]))

#define CP16(dst, src)                                                     \
    asm volatile("cp.async.ca.shared.global [%0], [%1], 16;"               \
        :: "r"(dst), "l"(src))
#define CP_COMMIT()  asm volatile("cp.async.commit_group;")
#define CP_WAIT(n)   asm volatile("cp.async.wait_group %0;" :: "n"(n))

// ---------------- kernel 0a: tf32-round a float array ----------------
__global__ __launch_bounds__(256) void cvt_tf32_kernel(
    const float* __restrict__ in, float* __restrict__ out)
{
    const int i = blockIdx.x * 256 + threadIdx.x;
    float4 v = ((const float4*)in)[i];
    v.x = rnd_tf32(v.x); v.y = rnd_tf32(v.y);
    v.z = rnd_tf32(v.z); v.w = rnd_tf32(v.w);
    ((float4*)out)[i] = v;
}

// ---------------- kernel 0b: RoPE table (fp64 once per (s,freq)) ----------
__global__ __launch_bounds__(256) void rope_tab_kernel(float2* __restrict__ tab)
{
    const int i = blockIdx.x * 256 + threadIdx.x;   // 0..65535
    const int s = i >> 5, f = i & 31;
    double invf = exp(-0.28782313662425575 * (double)f); // ln(10000)/32
    double sn, cs;
    sincos((double)s * invf, &sn, &cs);
    tab[i] = make_float2((float)cs, (float)sn);
}

// ---------------- kernel 1: LayerNorm (emits tf32-rounded xn) ----------------
__global__ __launch_bounds__(256) void ln_kernel(
    const float* __restrict__ x, const float* __restrict__ g,
    const float* __restrict__ b, float* __restrict__ y)
{
    __shared__ float red[16];
    const int row = blockIdx.x, tid = threadIdx.x;
    const float* xr = x + (size_t)row * D_;
    float4 v = *(const float4*)(xr + (tid << 2));
    float s  = v.x + v.y + v.z + v.w;
    float ss = v.x*v.x + v.y*v.y + v.z*v.z + v.w*v.w;
#pragma unroll
    for (int off = 16; off; off >>= 1) {
        s  += __shfl_xor_sync(0xffffffffu, s,  off);
        ss += __shfl_xor_sync(0xffffffffu, ss, off);
    }
    if ((tid & 31) == 0) { red[tid >> 5] = s; red[8 + (tid >> 5)] = ss; }
    __syncthreads();
    if (tid < 8) {
        float a = red[tid], c = red[8 + tid];
#pragma unroll
        for (int off = 4; off; off >>= 1) {
            a += __shfl_xor_sync(0xffu, a, off);
            c += __shfl_xor_sync(0xffu, c, off);
        }
        if (tid == 0) { red[0] = a; red[8] = c; }
    }
    __syncthreads();
    const float mean = red[0] * (1.f / 1024.f);
    const float var  = red[8] * (1.f / 1024.f) - mean * mean;
    const float r    = rsqrtf(var + 1e-6f);
    float4 gv = *(const float4*)(g + (tid << 2));
    float4 bv = *(const float4*)(b + (tid << 2));
    float4 o;
    o.x = rnd_tf32((v.x - mean) * r * gv.x + bv.x);
    o.y = rnd_tf32((v.y - mean) * r * gv.y + bv.y);
    o.z = rnd_tf32((v.z - mean) * r * gv.z + bv.z);
    o.w = rnd_tf32((v.w - mean) * r * gv.w + bv.w);
    *(float4*)(y + (size_t)row * D_ + (tid << 2)) = o;
}

// ---------------- kernel 2/5: tf32 GEMM + bias, cp.async 3-stage ----------
// A, Bm must already be tf32-rounded. C = A @ Bm + bias.
__global__ __launch_bounds__(256) void tf32_gemm_bias(
    const float* __restrict__ A, const float* __restrict__ Bm,
    const float* __restrict__ bias, float* __restrict__ C,
    int M, int N, int K)
{
    constexpr int AP = 20, BP = 136;
    constexpr int ASZ = 128 * AP;   // uints per A stage
    constexpr int BSZ = 16 * BP;    // uints per B stage
    extern __shared__ uint32_t gsm[];
    uint32_t* As = gsm;             // 3 stages
    uint32_t* Bs = gsm + 3 * ASZ;

    const int tid  = threadIdx.x;
    const int wid  = tid >> 5, lane = tid & 31;
    const int g    = lane >> 2, t = lane & 3;
    const int wm   = wid & 1;
    const int wn   = wid >> 1;
    const int m0   = blockIdx.y << 7, n0 = blockIdx.x << 7;

    const uint32_t smemB = (uint32_t)__cvta_generic_to_shared(gsm);

    float acc[4][4][4];
#pragma unroll
    for (int mi = 0; mi < 4; mi++)
#pragma unroll
        for (int ni = 0; ni < 4; ni++)
#pragma unroll
            for (int r = 0; r < 4; r++) acc[mi][ni][r] = 0.f;

    auto load_stage = [&](int st, int ks) {
        const float* Asrc = A  + (size_t)m0 * K + ks * 16;
        const float* Bsrc = Bm + (size_t)(ks * 16) * N + n0;
        const uint32_t aB = smemB + (st * ASZ) * 4;
        const uint32_t bB = smemB + (3 * ASZ + st * BSZ) * 4;
#pragma unroll
        for (int it = 0; it < 2; ++it) {
            const int c  = tid + (it << 8);
            const int ar = c >> 2,  ak = (c & 3) << 2;
            CP16(aB + (ar * AP + ak) * 4, Asrc + (size_t)ar * K + ak);
            const int br = c >> 5,  bc = (c & 31) << 2;
            CP16(bB + (br * BP + bc) * 4, Bsrc + (size_t)br * N + bc);
        }
    };

    load_stage(0, 0); CP_COMMIT();
    load_stage(1, 1); CP_COMMIT();

    const int KSTEPS = K >> 4;
    for (int ks = 0; ks < KSTEPS; ++ks) {
        CP_WAIT(1);
        __syncthreads();
        const int buf = ks % 3;
        const uint32_t* Ab = As + buf * ASZ;
        const uint32_t* Bb = Bs + buf * BSZ;

#pragma unroll
        for (int kk = 0; kk < 16; kk += 8) {
            uint32_t af[4][4], bfr[4][2];
#pragma unroll
            for (int mi = 0; mi < 4; mi++) {
                const int rb = wm * 64 + mi * 16;
                af[mi][0] = Ab[(rb + g)     * AP + kk + t];
                af[mi][1] = Ab[(rb + 8 + g) * AP + kk + t];
                af[mi][2] = Ab[(rb + g)     * AP + kk + t + 4];
                af[mi][3] = Ab[(rb + 8 + g) * AP + kk + t + 4];
            }
#pragma unroll
            for (int ni = 0; ni < 4; ni++) {
                const int cb = wn * 32 + ni * 8 + g;
                bfr[ni][0] = Bb[(kk + t)     * BP + cb];
                bfr[ni][1] = Bb[(kk + t + 4) * BP + cb];
            }
#pragma unroll
            for (int mi = 0; mi < 4; mi++)
#pragma unroll
                for (int ni = 0; ni < 4; ni++)
                    MMA_TF32(acc[mi][ni], af[mi], bfr[ni]);
        }

        if (ks + 2 < KSTEPS) load_stage((ks + 2) % 3, ks + 2);
        CP_COMMIT();
    }

#pragma unroll
    for (int mi = 0; mi < 4; mi++) {
        const int row0 = m0 + wm * 64 + mi * 16 + g;
#pragma unroll
        for (int ni = 0; ni < 4; ni++) {
            const int col = n0 + wn * 32 + ni * 8 + 2 * t;
            float2 bb = *(const float2*)(bias + col);
            float2 v0 = { acc[mi][ni][0] + bb.x, acc[mi][ni][1] + bb.y };
            float2 v1 = { acc[mi][ni][2] + bb.x, acc[mi][ni][3] + bb.y };
            *(float2*)(C + (size_t)row0 * N + col)       = v0;
            *(float2*)(C + (size_t)(row0 + 8) * N + col) = v1;
        }
    }
}

// ---------------- kernel 3: per-head LN + RoPE -> bf16 hi/lo ----------------
__device__ __forceinline__ float warp_allreduce_sum(float v) {
#pragma unroll
    for (int off = 16; off; off >>= 1) v += __shfl_xor_sync(0xffffffffu, v, off);
    return v;
}

__device__ __forceinline__ void split_store(
    __nv_bfloat16* hi, __nv_bfloat16* lo, size_t idx, float x)
{
    __nv_bfloat16 h = __float2bfloat16_rn(x);
    hi[idx] = h;
    lo[idx] = __float2bfloat16_rn(x - __bfloat162float(h));
}

__global__ __launch_bounds__(512) void qk_rope_kernel(
    const float* __restrict__ qkv, const float2* __restrict__ tab,
    const float* __restrict__ qsc, const float* __restrict__ ksc,
    __nv_bfloat16* __restrict__ Qh, __nv_bfloat16* __restrict__ Ql,
    __nv_bfloat16* __restrict__ Kh, __nv_bfloat16* __restrict__ Kl,
    __nv_bfloat16* __restrict__ Vh, __nv_bfloat16* __restrict__ Vl)
{
    const int bs   = blockIdx.x;
    const int b    = bs >> 11;
    const int s    = bs & (S_ - 1);
    const int h    = threadIdx.x >> 5;
    const int lane = threadIdx.x & 31;
    const float* base = qkv + (size_t)bs * (3 * D_) + h * HD_;

    float q0 = base[lane],        q1 = base[lane + 32];
    float k0 = base[1024 + lane], k1 = base[1024 + lane + 32];
    float v0 = base[2048 + lane], v1 = base[2048 + lane + 32];

    float mu  = warp_allreduce_sum(q0 + q1) * (1.f / 64.f);
    float d0  = q0 - mu, d1 = q1 - mu;
    float var = warp_allreduce_sum(d0*d0 + d1*d1) * (1.f / 64.f);
    float r   = rsqrtf(var + 1e-6f);
    float qn0 = d0 * r * qsc[lane];
    float qn1 = d1 * r * qsc[lane + 32];

    mu  = warp_allreduce_sum(k0 + k1) * (1.f / 64.f);
    d0  = k0 - mu; d1 = k1 - mu;
    var = warp_allreduce_sum(d0*d0 + d1*d1) * (1.f / 64.f);
    r   = rsqrtf(var + 1e-6f);
    float kn0 = d0 * r * ksc[lane];
    float kn1 = d1 * r * ksc[lane + 32];

    const float2 cs = tab[(s << 5) + lane];
    const float c = cs.x, si = cs.y;

    float qr0 = qn0 * c - qn1 * si;
    float qr1 = qn1 * c + qn0 * si;
    float kr0 = kn0 * c - kn1 * si;
    float kr1 = kn1 * c + kn0 * si;

    const size_t o = (((size_t)(b * H_ + h)) * S_ + s) * HD_ + lane;
    split_store(Qh, Ql, o,      qr0);
    split_store(Qh, Ql, o + 32, qr1);
    split_store(Kh, Kl, o,      kr0);
    split_store(Kh, Kl, o + 32, kr1);
    split_store(Vh, Vl, o,      v0);
    split_store(Vh, Vl, o + 32, v1);
}

// ---------------- bf16 mma helpers for attention ----------------
#define LDSM_X4(r0,r1,r2,r3,addr)                                          \
    asm volatile("ldmatrix.sync.aligned.m8n8.x4.shared.b16 {%0,%1,%2,%3}, [%4];" \
        : "=r"(r0), "=r"(r1), "=r"(r2), "=r"(r3) : "r"(addr))

#define LDSM_X4T(r0,r1,r2,r3,addr)                                         \
    asm volatile("ldmatrix.sync.aligned.m8n8.x4.trans.shared.b16 {%0,%1,%2,%3}, [%4];" \
        : "=r"(r0), "=r"(r1), "=r"(r2), "=r"(r3) : "r"(addr))

#define MMA_BF16(d, a0,a1,a2,a3, b0,b1)                                    \
    asm volatile("mma.sync.aligned.m16n8k16.row.col.f32.bf16.bf16.f32 "    \
        "{%0,%1,%2,%3}, {%4,%5,%6,%7}, {%8,%9}, {%0,%1,%2,%3};"            \
        : "+f"((d)[0]), "+f"((d)[1]), "+f"((d)[2]), "+f"((d)[3])           \
        : "r"(a0), "r"(a1), "r"(a2), "r"(a3), "r"(b0), "r"(b1))

__device__ __forceinline__ float ex2f(float x) {
    float y; asm("ex2.approx.f32 %0, %1;" : "=f"(y) : "f"(x)); return y;
}

#define TP 72
#define TSZ (64 * TP)          // halfs per 64x64 tile

__device__ __forceinline__ void cp_tile(
    uint32_t dst, const __nv_bfloat16* __restrict__ src, int tid)
{
#pragma unroll
    for (int it = 0; it < 4; ++it) {
        int c = tid + (it << 7);       // 0..511 chunks of 16B
        int r = c >> 3, cc = c & 7;
        CP16(dst + r * (TP * 2) + cc * 16, src + r * HD_ + cc * 8);
    }
}

// ---------------- kernel 4: tensor-core flash attention (bf16x3) ----------
__global__ __launch_bounds__(128, 3) void attn_kernel(
    const __nv_bfloat16* __restrict__ Qh, const __nv_bfloat16* __restrict__ Ql,
    const __nv_bfloat16* __restrict__ Kh, const __nv_bfloat16* __restrict__ Kl,
    const __nv_bfloat16* __restrict__ Vh, const __nv_bfloat16* __restrict__ Vl,
    float* __restrict__ O)
{
    extern __shared__ __nv_bfloat16 sh[];   // [2 stages][4 tiles][TSZ]

    const int tid  = threadIdx.x;
    const int lane = tid & 31, w = tid >> 5;
    const int g    = lane >> 2, t = lane & 3;
    const int bh   = blockIdx.y;
    const int q0   = blockIdx.x << 6;

    const __nv_bfloat16* Kbh = Kh + (size_t)bh * S_ * HD_;
    const __nv_bfloat16* Kbl = Kl + (size_t)bh * S_ * HD_;
    const __nv_bfloat16* Vbh = Vh + (size_t)bh * S_ * HD_;
    const __nv_bfloat16* Vbl = Vl + (size_t)bh * S_ * HD_;

    const uint32_t shB = (uint32_t)__cvta_generic_to_shared(sh);

    // ---- Q A-fragments straight from gmem (once) ----
    uint32_t qhf[4][4], qlf[4][4];
    {
        const __nv_bfloat16* Qbase = Qh + ((size_t)bh * S_ + q0 + (w << 4)) * HD_;
        const __nv_bfloat16* Qbl   = Ql + ((size_t)bh * S_ + q0 + (w << 4)) * HD_;
#pragma unroll
        for (int kb = 0; kb < 4; ++kb) {
            const int c0 = kb * 16 + 2 * t;
            qhf[kb][0] = *(const uint32_t*)(Qbase + (size_t)g       * HD_ + c0);
            qhf[kb][1] = *(const uint32_t*)(Qbase + (size_t)(g + 8) * HD_ + c0);
            qhf[kb][2] = *(const uint32_t*)(Qbase + (size_t)g       * HD_ + c0 + 8);
            qhf[kb][3] = *(const uint32_t*)(Qbase + (size_t)(g + 8) * HD_ + c0 + 8);
            qlf[kb][0] = *(const uint32_t*)(Qbl   + (size_t)g       * HD_ + c0);
            qlf[kb][1] = *(const uint32_t*)(Qbl   + (size_t)(g + 8) * HD_ + c0);
            qlf[kb][2] = *(const uint32_t*)(Qbl   + (size_t)g       * HD_ + c0 + 8);
            qlf[kb][3] = *(const uint32_t*)(Qbl   + (size_t)(g + 8) * HD_ + c0 + 8);
        }
    }

    // x4 ldmatrix lane offsets (bytes)
    const uint32_t kx4 = ((((lane >> 4) << 3) + (lane & 7)) * TP
                          + ((lane >> 3) & 1) * 8) * 2;
    const uint32_t vx4 = (((((lane >> 3) & 1) << 3) + (lane & 7)) * TP
                          + ((lane >> 4) & 1) * 8) * 2;

    float m0 = -1e30f, m1 = -1e30f, l0 = 0.f, l1 = 0.f;
    float o_[8][4];
#pragma unroll
    for (int nb = 0; nb < 8; nb++)
#pragma unroll
        for (int j = 0; j < 4; j++) o_[nb][j] = 0.f;

    const float SCALE = 0.18033688011112042f;  // log2(e)/8

    {
        const uint32_t st0 = shB;
        cp_tile(st0,                Kbh, tid);
        cp_tile(st0 + TSZ * 2,      Kbl, tid);
        cp_tile(st0 + 2 * TSZ * 2,  Vbh, tid);
        cp_tile(st0 + 3 * TSZ * 2,  Vbl, tid);
        CP_COMMIT();
    }

    int buf = 0;
    for (int kt = 0; kt < S_; kt += 64) {
        if (kt + 64 < S_) {
            const uint32_t stn = shB + (buf ^ 1) * 4 * TSZ * 2;
            const size_t goff = (size_t)(kt + 64) * HD_;
            cp_tile(stn,               Kbh + goff, tid);
            cp_tile(stn + TSZ * 2,     Kbl + goff, tid);
            cp_tile(stn + 2 * TSZ * 2, Vbh + goff, tid);
            cp_tile(stn + 3 * TSZ * 2, Vbl + goff, tid);
            CP_COMMIT();
            CP_WAIT(1);
        } else {
            CP_WAIT(0);
        }
        __syncthreads();

        const uint32_t KhiB = shB + buf * 4 * TSZ * 2;
        const uint32_t KloB = KhiB + TSZ * 2;
        const uint32_t VhiB = KhiB + 2 * TSZ * 2;
        const uint32_t VloB = KhiB + 3 * TSZ * 2;

        // ---- S = Q K^T (warp: 16 x 64), bf16x3, x4 ldmatrix ----
        float S[8][4];
#pragma unroll
        for (int nb = 0; nb < 8; nb++)
#pragma unroll
            for (int j = 0; j < 4; j++) S[nb][j] = 0.f;

#pragma unroll
        for (int nb = 0; nb < 8; nb += 2) {
#pragma unroll
            for (int kb = 0; kb < 4; ++kb) {
                const uint32_t off = kx4 + (nb * 8 * TP + kb * 16) * 2;
                uint32_t h0, h1, h2, h3, e0, e1, e2, e3;
                LDSM_X4(h0, h1, h2, h3, KhiB + off);
                LDSM_X4(e0, e1, e2, e3, KloB + off);
                MMA_BF16(S[nb],   qhf[kb][0], qhf[kb][1], qhf[kb][2], qhf[kb][3], h0, h1);
                MMA_BF16(S[nb],   qhf[kb][0], qhf[kb][1], qhf[kb][2], qhf[kb][3], e0, e1);
                MMA_BF16(S[nb],   qlf[kb][0], qlf[kb][1], qlf[kb][2], qlf[kb][3], h0, h1);
                MMA_BF16(S[nb+1], qhf[kb][0], qhf[kb][1], qhf[kb][2], qhf[kb][3], h2, h3);
                MMA_BF16(S[nb+1], qhf[kb][0], qhf[kb][1], qhf[kb][2], qhf[kb][3], e2, e3);
                MMA_BF16(S[nb+1], qlf[kb][0], qlf[kb][1], qlf[kb][2], qlf[kb][3], h2, h3);
            }
        }

        // ---- online softmax ----
        float tm0 = -1e30f, tm1 = -1e30f;
#pragma unroll
        for (int nb = 0; nb < 8; ++nb) {
            S[nb][0] *= SCALE; S[nb][1] *= SCALE;
            S[nb][2] *= SCALE; S[nb][3] *= SCALE;
            tm0 = fmaxf(tm0, fmaxf(S[nb][0], S[nb][1]));
            tm1 = fmaxf(tm1, fmaxf(S[nb][2], S[nb][3]));
        }
        tm0 = fmaxf(tm0, __shfl_xor_sync(0xffffffffu, tm0, 1));
        tm0 = fmaxf(tm0, __shfl_xor_sync(0xffffffffu, tm0, 2));
        tm1 = fmaxf(tm1, __shfl_xor_sync(0xffffffffu, tm1, 1));
        tm1 = fmaxf(tm1, __shfl_xor_sync(0xffffffffu, tm1, 2));

        const float nm0 = fmaxf(m0, tm0), nm1 = fmaxf(m1, tm1);
        const float a0 = ex2f(m0 - nm0),  a1 = ex2f(m1 - nm1);
        m0 = nm0; m1 = nm1;

        float rs0 = 0.f, rs1 = 0.f;
#pragma unroll
        for (int nb = 0; nb < 8; ++nb) {
            S[nb][0] = ex2f(S[nb][0] - m0);
            S[nb][1] = ex2f(S[nb][1] - m0);
            S[nb][2] = ex2f(S[nb][2] - m1);
            S[nb][3] = ex2f(S[nb][3] - m1);
            rs0 += S[nb][0] + S[nb][1];
            rs1 += S[nb][2] + S[nb][3];
        }
        rs0 += __shfl_xor_sync(0xffffffffu, rs0, 1);
        rs0 += __shfl_xor_sync(0xffffffffu, rs0, 2);
        rs1 += __shfl_xor_sync(0xffffffffu, rs1, 1);
        rs1 += __shfl_xor_sync(0xffffffffu, rs1, 2);
        l0 = l0 * a0 + rs0;
        l1 = l1 * a1 + rs1;
#pragma unroll
        for (int nb = 0; nb < 8; ++nb) {
            o_[nb][0] *= a0; o_[nb][1] *= a0;
            o_[nb][2] *= a1; o_[nb][3] *= a1;
        }

        // ---- O += P V  (bf16x3; x4 trans ldmatrix) ----
#pragma unroll
        for (int kb = 0; kb < 4; ++kb) {
            uint32_t phi[4], plo[4];
#pragma unroll
            for (int half = 0; half < 2; ++half) {
                const float c0 = S[2 * kb + half][0], c1 = S[2 * kb + half][1];
                const float c2 = S[2 * kb + half][2], c3 = S[2 * kb + half][3];
                __nv_bfloat162 h0 = __floats2bfloat162_rn(c0, c1);
                __nv_bfloat162 h1 = __floats2bfloat162_rn(c2, c3);
                __nv_bfloat162 e0 = __floats2bfloat162_rn(c0 - __bfloat162float(h0.x),
                                                          c1 - __bfloat162float(h0.y));
                __nv_bfloat162 e1 = __floats2bfloat162_rn(c2 - __bfloat162float(h1.x),
                                                          c3 - __bfloat162float(h1.y));
                phi[2 * half]     = *(uint32_t*)&h0;
                phi[2 * half + 1] = *(uint32_t*)&h1;
                plo[2 * half]     = *(uint32_t*)&e0;
                plo[2 * half + 1] = *(uint32_t*)&e1;
            }
#pragma unroll
            for (int nb = 0; nb < 8; nb += 2) {
                const uint32_t off = vx4 + (kb * 16 * TP + nb * 8) * 2;
                uint32_t vh0, vh1, vh2, vh3, vl0, vl1, vl2, vl3;
                LDSM_X4T(vh0, vh1, vh2, vh3, VhiB + off);
                LDSM_X4T(vl0, vl1, vl2, vl3, VloB + off);
                MMA_BF16(o_[nb],   phi[0], phi[1], phi[2], phi[3], vh0, vh1);
                MMA_BF16(o_[nb],   phi[0], phi[1], phi[2], phi[3], vl0, vl1);
                MMA_BF16(o_[nb],   plo[0], plo[1], plo[2], plo[3], vh0, vh1);
                MMA_BF16(o_[nb+1], phi[0], phi[1], phi[2], phi[3], vh2, vh3);
                MMA_BF16(o_[nb+1], phi[0], phi[1], phi[2], phi[3], vl2, vl3);
                MMA_BF16(o_[nb+1], plo[0], plo[1], plo[2], plo[3], vh2, vh3);
            }
        }
        __syncthreads();
        buf ^= 1;
    }

    // ---- epilogue: O /= l, tf32-round (feeds out-proj GEMM) ----
    const int b = bh >> 4, h = bh & 15;
    const float inv0 = 1.f / l0, inv1 = 1.f / l1;
    const int row0 = q0 + (w << 4) + g;
#pragma unroll
    for (int nb = 0; nb < 8; ++nb) {
        const int col = h * HD_ + nb * 8 + 2 * t;
        float2 v0 = { rnd_tf32(o_[nb][0] * inv0), rnd_tf32(o_[nb][1] * inv0) };
        float2 v1 = { rnd_tf32(o_[nb][2] * inv1), rnd_tf32(o_[nb][3] * inv1) };
        *(float2*)(O + (size_t)(b * S_ + row0) * D_ + col)     = v0;
        *(float2*)(O + (size_t)(b * S_ + row0 + 8) * D_ + col) = v1;
    }
}

// ---------------- launch ----------------
extern "C" void kernel_launch(void* const* d_in, const int* in_sizes, int n_in,
                              void* d_out, int out_size)
{
    const float* x        = (const float*)d_in[0];
    const float* w_qkv    = (const float*)d_in[1];
    const float* b_qkv    = (const float*)d_in[2];
    const float* w_out    = (const float*)d_in[3];
    const float* b_out    = (const float*)d_in[4];
    const float* ln_scale = (const float*)d_in[5];
    const float* ln_bias  = (const float*)d_in[6];
    const float* q_scale  = (const float*)d_in[7];
    const float* k_scale  = (const float*)d_in[8];
    float* out = (float*)d_out;

    float *xn, *qkv, *attn, *wqt, *wot;
    float2* rtab;
    __nv_bfloat16 *qh, *ql, *kh, *kl, *vh, *vl;
    cudaGetSymbolAddress((void**)&xn,   g_xn);
    cudaGetSymbolAddress((void**)&qkv,  g_qkv);
    cudaGetSymbolAddress((void**)&attn, g_attn);
    cudaGetSymbolAddress((void**)&wqt,  g_wqt);
    cudaGetSymbolAddress((void**)&wot,  g_wot);
    cudaGetSymbolAddress((void**)&rtab, g_rtab);
    cudaGetSymbolAddress((void**)&qh,   g_qh);
    cudaGetSymbolAddress((void**)&ql,   g_ql);
    cudaGetSymbolAddress((void**)&kh,   g_kh);
    cudaGetSymbolAddress((void**)&kl,   g_kl);
    cudaGetSymbolAddress((void**)&vh,   g_vh);
    cudaGetSymbolAddress((void**)&vl,   g_vl);

    const int attn_smem = 2 * 4 * TSZ * sizeof(__nv_bfloat16);       // 73728 B
    const int gemm_smem = 3 * (128 * 20 + 16 * 136) * sizeof(uint32_t); // 56832 B
    cudaFuncSetAttribute(attn_kernel, cudaFuncAttributeMaxDynamicSharedMemorySize, attn_smem);
    cudaFuncSetAttribute(tf32_gemm_bias, cudaFuncAttributeMaxDynamicSharedMemorySize, gemm_smem);

    cvt_tf32_kernel<<<(D_ * 3 * D_) / 1024, 256>>>(w_qkv, wqt);
    cvt_tf32_kernel<<<(D_ * D_) / 1024, 256>>>(w_out, wot);
    rope_tab_kernel<<<(S_ * 32) / 256, 256>>>(rtab);
    ln_kernel<<<ROWS_, 256>>>(x, ln_scale, ln_bias, xn);
    tf32_gemm_bias<<<dim3((3 * D_) / 128, ROWS_ / 128), 256, gemm_smem>>>(
        xn, wqt, b_qkv, qkv, ROWS_, 3 * D_, D_);
    qk_rope_kernel<<<ROWS_, 512>>>(qkv, rtab, q_scale, k_scale, qh, ql, kh, kl, vh, vl);
    attn_kernel<<<dim3(S_ / 64, B_ * H_), 128, attn_smem>>>(qh, ql, kh, kl, vh, vl, attn);
    tf32_gemm_bias<<<dim3(D_ / 128, ROWS_ / 128), 256, gemm_smem>>>(
        attn, wot, b_out, out, ROWS_, D_, D_);
}

// round 9
// speedup vs baseline: 3.6799x; 1.0196x over previous
#include <cuda_runtime.h>
#include <cuda_bf16.h>
#include <stdint.h>
#include <math.h>

#define B_  2
#define S_  2048
#define D_  1024
#define H_  16
#define HD_ 64
#define ROWS_ (B_*S_)   // 4096

// ---------------- scratch (device globals; no allocations) ----------------
__device__ float g_xn  [ROWS_*D_];
__device__ float g_qkv [ROWS_*3*D_];
__device__ float g_attn[ROWS_*D_];
__device__ float g_wqt [D_*3*D_];     // tf32-rounded w_qkv
__device__ float g_wot [D_*D_];       // tf32-rounded w_out
__device__ float2 g_rtab[S_*32];      // RoPE cos/sin table
__device__ __nv_bfloat16 g_qh[B_*H_*S_*HD_];
__device__ __nv_bfloat16 g_ql[B_*H_*S_*HD_];
__device__ __nv_bfloat16 g_kh[B_*H_*S_*HD_];
__device__ __nv_bfloat16 g_kl[B_*H_*S_*HD_];
__device__ __nv_bfloat16 g_vh[B_*H_*S_*HD_];
__device__ __nv_bfloat16 g_vl[B_*H_*S_*HD_];

// ---------------- helpers ----------------
__device__ __forceinline__ uint32_t f2tf32(float x) {
    uint32_t r;
    asm("cvt.rna.tf32.f32 %0, %1;" : "=r"(r) : "f"(x));
    return r;
}
__device__ __forceinline__ float rnd_tf32(float x) {
    return __uint_as_float(f2tf32(x));
}

#define MMA_TF32(d, a, b)                                              \
    asm volatile("mma.sync.aligned.m16n8k8.row.col.f32.tf32.tf32.f32 " \
        "{%0,%1,%2,%3}, {%4,%5,%6,%7}, {%8,%9}, {%0,%1,%2,%3};"        \
        : "+f"((d)[0]), "+f"((d)[1]), "+f"((d)[2]), "+f"((d)[3])       \
        : "r"((a)[0]), "r"((a)[1]), "r"((a)[2]), "r"((a)[3]),          \
          "r"((b)[0]), "r"((b)[1]))

#define CP16(dst, src)                                                     \
    asm volatile("cp.async.ca.shared.global [%0], [%1], 16;"               \
        :: "r"(dst), "l"(src))
#define CP_COMMIT()  asm volatile("cp.async.commit_group;")
#define CP_WAIT(n)   asm volatile("cp.async.wait_group %0;" :: "n"(n))

// ---------------- kernel 0a: tf32-round a float array ----------------
__global__ __launch_bounds__(256) void cvt_tf32_kernel(
    const float* __restrict__ in, float* __restrict__ out)
{
    const int i = blockIdx.x * 256 + threadIdx.x;
    float4 v = ((const float4*)in)[i];
    v.x = rnd_tf32(v.x); v.y = rnd_tf32(v.y);
    v.z = rnd_tf32(v.z); v.w = rnd_tf32(v.w);
    ((float4*)out)[i] = v;
}

// ---------------- kernel 0b: RoPE table (fp64 once per (s,freq)) ----------
__global__ __launch_bounds__(256) void rope_tab_kernel(float2* __restrict__ tab)
{
    const int i = blockIdx.x * 256 + threadIdx.x;   // 0..65535
    const int s = i >> 5, f = i & 31;
    double invf = exp(-0.28782313662425575 * (double)f); // ln(10000)/32
    double sn, cs;
    sincos((double)s * invf, &sn, &cs);
    tab[i] = make_float2((float)cs, (float)sn);
}

// ---------------- kernel 1: LayerNorm (emits tf32-rounded xn) ----------------
__global__ __launch_bounds__(256) void ln_kernel(
    const float* __restrict__ x, const float* __restrict__ g,
    const float* __restrict__ b, float* __restrict__ y)
{
    __shared__ float red[16];
    const int row = blockIdx.x, tid = threadIdx.x;
    const float* xr = x + (size_t)row * D_;
    float4 v = *(const float4*)(xr + (tid << 2));
    float s  = v.x + v.y + v.z + v.w;
    float ss = v.x*v.x + v.y*v.y + v.z*v.z + v.w*v.w;
#pragma unroll
    for (int off = 16; off; off >>= 1) {
        s  += __shfl_xor_sync(0xffffffffu, s,  off);
        ss += __shfl_xor_sync(0xffffffffu, ss, off);
    }
    if ((tid & 31) == 0) { red[tid >> 5] = s; red[8 + (tid >> 5)] = ss; }
    __syncthreads();
    if (tid < 8) {
        float a = red[tid], c = red[8 + tid];
#pragma unroll
        for (int off = 4; off; off >>= 1) {
            a += __shfl_xor_sync(0xffu, a, off);
            c += __shfl_xor_sync(0xffu, c, off);
        }
        if (tid == 0) { red[0] = a; red[8] = c; }
    }
    __syncthreads();
    const float mean = red[0] * (1.f / 1024.f);
    const float var  = red[8] * (1.f / 1024.f) - mean * mean;
    const float r    = rsqrtf(var + 1e-6f);
    float4 gv = *(const float4*)(g + (tid << 2));
    float4 bv = *(const float4*)(b + (tid << 2));
    float4 o;
    o.x = rnd_tf32((v.x - mean) * r * gv.x + bv.x);
    o.y = rnd_tf32((v.y - mean) * r * gv.y + bv.y);
    o.z = rnd_tf32((v.z - mean) * r * gv.z + bv.z);
    o.w = rnd_tf32((v.w - mean) * r * gv.w + bv.w);
    *(float4*)(y + (size_t)row * D_ + (tid << 2)) = o;
}

// ---------------- kernel 2/5: tf32 GEMM + bias, cp.async 3-stage ----------
__global__ __launch_bounds__(256) void tf32_gemm_bias(
    const float* __restrict__ A, const float* __restrict__ Bm,
    const float* __restrict__ bias, float* __restrict__ C,
    int M, int N, int K)
{
    constexpr int AP = 20, BP = 136;
    constexpr int ASZ = 128 * AP;
    constexpr int BSZ = 16 * BP;
    extern __shared__ uint32_t gsm[];
    uint32_t* As = gsm;
    uint32_t* Bs = gsm + 3 * ASZ;

    const int tid  = threadIdx.x;
    const int wid  = tid >> 5, lane = tid & 31;
    const int g    = lane >> 2, t = lane & 3;
    const int wm   = wid & 1;
    const int wn   = wid >> 1;
    const int m0   = blockIdx.y << 7, n0 = blockIdx.x << 7;

    const uint32_t smemB = (uint32_t)__cvta_generic_to_shared(gsm);

    float acc[4][4][4];
#pragma unroll
    for (int mi = 0; mi < 4; mi++)
#pragma unroll
        for (int ni = 0; ni < 4; ni++)
#pragma unroll
            for (int r = 0; r < 4; r++) acc[mi][ni][r] = 0.f;

    auto load_stage = [&](int st, int ks) {
        const float* Asrc = A  + (size_t)m0 * K + ks * 16;
        const float* Bsrc = Bm + (size_t)(ks * 16) * N + n0;
        const uint32_t aB = smemB + (st * ASZ) * 4;
        const uint32_t bB = smemB + (3 * ASZ + st * BSZ) * 4;
#pragma unroll
        for (int it = 0; it < 2; ++it) {
            const int c  = tid + (it << 8);
            const int ar = c >> 2,  ak = (c & 3) << 2;
            CP16(aB + (ar * AP + ak) * 4, Asrc + (size_t)ar * K + ak);
            const int br = c >> 5,  bc = (c & 31) << 2;
            CP16(bB + (br * BP + bc) * 4, Bsrc + (size_t)br * N + bc);
        }
    };

    load_stage(0, 0); CP_COMMIT();
    load_stage(1, 1); CP_COMMIT();

    const int KSTEPS = K >> 4;
    for (int ks = 0; ks < KSTEPS; ++ks) {
        CP_WAIT(1);
        __syncthreads();
        const int buf = ks % 3;
        const uint32_t* Ab = As + buf * ASZ;
        const uint32_t* Bb = Bs + buf * BSZ;

#pragma unroll
        for (int kk = 0; kk < 16; kk += 8) {
            uint32_t af[4][4], bfr[4][2];
#pragma unroll
            for (int mi = 0; mi < 4; mi++) {
                const int rb = wm * 64 + mi * 16;
                af[mi][0] = Ab[(rb + g)     * AP + kk + t];
                af[mi][1] = Ab[(rb + 8 + g) * AP + kk + t];
                af[mi][2] = Ab[(rb + g)     * AP + kk + t + 4];
                af[mi][3] = Ab[(rb + 8 + g) * AP + kk + t + 4];
            }
#pragma unroll
            for (int ni = 0; ni < 4; ni++) {
                const int cb = wn * 32 + ni * 8 + g;
                bfr[ni][0] = Bb[(kk + t)     * BP + cb];
                bfr[ni][1] = Bb[(kk + t + 4) * BP + cb];
            }
#pragma unroll
            for (int mi = 0; mi < 4; mi++)
#pragma unroll
                for (int ni = 0; ni < 4; ni++)
                    MMA_TF32(acc[mi][ni], af[mi], bfr[ni]);
        }

        if (ks + 2 < KSTEPS) load_stage((ks + 2) % 3, ks + 2);
        CP_COMMIT();
    }

#pragma unroll
    for (int mi = 0; mi < 4; mi++) {
        const int row0 = m0 + wm * 64 + mi * 16 + g;
#pragma unroll
        for (int ni = 0; ni < 4; ni++) {
            const int col = n0 + wn * 32 + ni * 8 + 2 * t;
            float2 bb = *(const float2*)(bias + col);
            float2 v0 = { acc[mi][ni][0] + bb.x, acc[mi][ni][1] + bb.y };
            float2 v1 = { acc[mi][ni][2] + bb.x, acc[mi][ni][3] + bb.y };
            *(float2*)(C + (size_t)row0 * N + col)       = v0;
            *(float2*)(C + (size_t)(row0 + 8) * N + col) = v1;
        }
    }
}

// ---------------- kernel 3: per-head LN + RoPE -> bf16 hi/lo ----------------
__device__ __forceinline__ float warp_allreduce_sum(float v) {
#pragma unroll
    for (int off = 16; off; off >>= 1) v += __shfl_xor_sync(0xffffffffu, v, off);
    return v;
}

__device__ __forceinline__ void split_store(
    __nv_bfloat16* hi, __nv_bfloat16* lo, size_t idx, float x)
{
    __nv_bfloat16 h = __float2bfloat16_rn(x);
    hi[idx] = h;
    lo[idx] = __float2bfloat16_rn(x - __bfloat162float(h));
}

__global__ __launch_bounds__(512) void qk_rope_kernel(
    const float* __restrict__ qkv, const float2* __restrict__ tab,
    const float* __restrict__ qsc, const float* __restrict__ ksc,
    __nv_bfloat16* __restrict__ Qh, __nv_bfloat16* __restrict__ Ql,
    __nv_bfloat16* __restrict__ Kh, __nv_bfloat16* __restrict__ Kl,
    __nv_bfloat16* __restrict__ Vh, __nv_bfloat16* __restrict__ Vl)
{
    const int bs   = blockIdx.x;
    const int b    = bs >> 11;
    const int s    = bs & (S_ - 1);
    const int h    = threadIdx.x >> 5;
    const int lane = threadIdx.x & 31;
    const float* base = qkv + (size_t)bs * (3 * D_) + h * HD_;

    float q0 = base[lane],        q1 = base[lane + 32];
    float k0 = base[1024 + lane], k1 = base[1024 + lane + 32];
    float v0 = base[2048 + lane], v1 = base[2048 + lane + 32];

    float mu  = warp_allreduce_sum(q0 + q1) * (1.f / 64.f);
    float d0  = q0 - mu, d1 = q1 - mu;
    float var = warp_allreduce_sum(d0*d0 + d1*d1) * (1.f / 64.f);
    float r   = rsqrtf(var + 1e-6f);
    float qn0 = d0 * r * qsc[lane];
    float qn1 = d1 * r * qsc[lane + 32];

    mu  = warp_allreduce_sum(k0 + k1) * (1.f / 64.f);
    d0  = k0 - mu; d1 = k1 - mu;
    var = warp_allreduce_sum(d0*d0 + d1*d1) * (1.f / 64.f);
    r   = rsqrtf(var + 1e-6f);
    float kn0 = d0 * r * ksc[lane];
    float kn1 = d1 * r * ksc[lane + 32];

    const float2 cs = tab[(s << 5) + lane];
    const float c = cs.x, si = cs.y;

    float qr0 = qn0 * c - qn1 * si;
    float qr1 = qn1 * c + qn0 * si;
    float kr0 = kn0 * c - kn1 * si;
    float kr1 = kn1 * c + kn0 * si;

    const size_t o = (((size_t)(b * H_ + h)) * S_ + s) * HD_ + lane;
    split_store(Qh, Ql, o,      qr0);
    split_store(Qh, Ql, o + 32, qr1);
    split_store(Kh, Kl, o,      kr0);
    split_store(Kh, Kl, o + 32, kr1);
    split_store(Vh, Vl, o,      v0);
    split_store(Vh, Vl, o + 32, v1);
}

// ---------------- bf16 mma helpers for attention ----------------
#define LDSM_X4(r0,r1,r2,r3,addr)                                          \
    asm volatile("ldmatrix.sync.aligned.m8n8.x4.shared.b16 {%0,%1,%2,%3}, [%4];" \
        : "=r"(r0), "=r"(r1), "=r"(r2), "=r"(r3) : "r"(addr))

#define LDSM_X4T(r0,r1,r2,r3,addr)                                         \
    asm volatile("ldmatrix.sync.aligned.m8n8.x4.trans.shared.b16 {%0,%1,%2,%3}, [%4];" \
        : "=r"(r0), "=r"(r1), "=r"(r2), "=r"(r3) : "r"(addr))

#define MMA_BF16(d, a0,a1,a2,a3, b0,b1)                                    \
    asm volatile("mma.sync.aligned.m16n8k16.row.col.f32.bf16.bf16.f32 "    \
        "{%0,%1,%2,%3}, {%4,%5,%6,%7}, {%8,%9}, {%0,%1,%2,%3};"            \
        : "+f"((d)[0]), "+f"((d)[1]), "+f"((d)[2]), "+f"((d)[3])           \
        : "r"(a0), "r"(a1), "r"(a2), "r"(a3), "r"(b0), "r"(b1))

__device__ __forceinline__ float ex2f(float x) {
    float y; asm("ex2.approx.f32 %0, %1;" : "=f"(y) : "f"(x)); return y;
}

#define TP 72
#define TSZ (64 * TP)          // halfs per 64x64 tile

__device__ __forceinline__ void cp_tile(
    uint32_t dst, const __nv_bfloat16* __restrict__ src, int tid)
{
#pragma unroll
    for (int it = 0; it < 4; ++it) {
        int c = tid + (it << 7);       // 0..511 chunks of 16B
        int r = c >> 3, cc = c & 7;
        CP16(dst + r * (TP * 2) + cc * 16, src + r * HD_ + cc * 8);
    }
}

// ---------------- kernel 4: flash attention (bf16x3, exact no-max softmax) --
// Scores are bounded: per-head LN gives ||q||=||k||=8, so |q.k|/8 <= 8.
// exp(8) ~ 3e3, row sum <= 2048*e^8 ~ 6e6 — fp32-safe without max subtraction.
__global__ __launch_bounds__(128, 3) void attn_kernel(
    const __nv_bfloat16* __restrict__ Qh, const __nv_bfloat16* __restrict__ Ql,
    const __nv_bfloat16* __restrict__ Kh, const __nv_bfloat16* __restrict__ Kl,
    const __nv_bfloat16* __restrict__ Vh, const __nv_bfloat16* __restrict__ Vl,
    float* __restrict__ O)
{
    extern __shared__ __nv_bfloat16 sh[];   // [2 stages][4 tiles][TSZ]

    const int tid  = threadIdx.x;
    const int lane = tid & 31, w = tid >> 5;
    const int g    = lane >> 2, t = lane & 3;
    const int bh   = blockIdx.y;
    const int q0   = blockIdx.x << 6;

    const __nv_bfloat16* Kbh = Kh + (size_t)bh * S_ * HD_;
    const __nv_bfloat16* Kbl = Kl + (size_t)bh * S_ * HD_;
    const __nv_bfloat16* Vbh = Vh + (size_t)bh * S_ * HD_;
    const __nv_bfloat16* Vbl = Vl + (size_t)bh * S_ * HD_;

    const uint32_t shB = (uint32_t)__cvta_generic_to_shared(sh);

    // ---- Q A-fragments straight from gmem (once) ----
    uint32_t qhf[4][4], qlf[4][4];
    {
        const __nv_bfloat16* Qbase = Qh + ((size_t)bh * S_ + q0 + (w << 4)) * HD_;
        const __nv_bfloat16* Qbl   = Ql + ((size_t)bh * S_ + q0 + (w << 4)) * HD_;
#pragma unroll
        for (int kb = 0; kb < 4; ++kb) {
            const int c0 = kb * 16 + 2 * t;
            qhf[kb][0] = *(const uint32_t*)(Qbase + (size_t)g       * HD_ + c0);
            qhf[kb][1] = *(const uint32_t*)(Qbase + (size_t)(g + 8) * HD_ + c0);
            qhf[kb][2] = *(const uint32_t*)(Qbase + (size_t)g       * HD_ + c0 + 8);
            qhf[kb][3] = *(const uint32_t*)(Qbase + (size_t)(g + 8) * HD_ + c0 + 8);
            qlf[kb][0] = *(const uint32_t*)(Qbl   + (size_t)g       * HD_ + c0);
            qlf[kb][1] = *(const uint32_t*)(Qbl   + (size_t)(g + 8) * HD_ + c0);
            qlf[kb][2] = *(const uint32_t*)(Qbl   + (size_t)g       * HD_ + c0 + 8);
            qlf[kb][3] = *(const uint32_t*)(Qbl   + (size_t)(g + 8) * HD_ + c0 + 8);
        }
    }

    const uint32_t kx4 = ((((lane >> 4) << 3) + (lane & 7)) * TP
                          + ((lane >> 3) & 1) * 8) * 2;
    const uint32_t vx4 = (((((lane >> 3) & 1) << 3) + (lane & 7)) * TP
                          + ((lane >> 4) & 1) * 8) * 2;

    float l0 = 0.f, l1 = 0.f;          // thread-local partial row sums
    float o_[8][4];
#pragma unroll
    for (int nb = 0; nb < 8; nb++)
#pragma unroll
        for (int j = 0; j < 4; j++) o_[nb][j] = 0.f;

    const float SCALE = 0.18033688011112042f;  // log2(e)/8

    {
        const uint32_t st0 = shB;
        cp_tile(st0,                Kbh, tid);
        cp_tile(st0 + TSZ * 2,      Kbl, tid);
        cp_tile(st0 + 2 * TSZ * 2,  Vbh, tid);
        cp_tile(st0 + 3 * TSZ * 2,  Vbl, tid);
        CP_COMMIT();
    }

    int buf = 0;
    for (int kt = 0; kt < S_; kt += 64) {
        if (kt + 64 < S_) {
            const uint32_t stn = shB + (buf ^ 1) * 4 * TSZ * 2;
            const size_t goff = (size_t)(kt + 64) * HD_;
            cp_tile(stn,               Kbh + goff, tid);
            cp_tile(stn + TSZ * 2,     Kbl + goff, tid);
            cp_tile(stn + 2 * TSZ * 2, Vbh + goff, tid);
            cp_tile(stn + 3 * TSZ * 2, Vbl + goff, tid);
            CP_COMMIT();
            CP_WAIT(1);
        } else {
            CP_WAIT(0);
        }
        __syncthreads();

        const uint32_t KhiB = shB + buf * 4 * TSZ * 2;
        const uint32_t KloB = KhiB + TSZ * 2;
        const uint32_t VhiB = KhiB + 2 * TSZ * 2;
        const uint32_t VloB = KhiB + 3 * TSZ * 2;

        // ---- S = Q K^T (warp: 16 x 64), bf16x3, x4 ldmatrix ----
        float S[8][4];
#pragma unroll
        for (int nb = 0; nb < 8; nb++)
#pragma unroll
            for (int j = 0; j < 4; j++) S[nb][j] = 0.f;

#pragma unroll
        for (int nb = 0; nb < 8; nb += 2) {
#pragma unroll
            for (int kb = 0; kb < 4; ++kb) {
                const uint32_t off = kx4 + (nb * 8 * TP + kb * 16) * 2;
                uint32_t h0, h1, h2, h3, e0, e1, e2, e3;
                LDSM_X4(h0, h1, h2, h3, KhiB + off);
                LDSM_X4(e0, e1, e2, e3, KloB + off);
                MMA_BF16(S[nb],   qhf[kb][0], qhf[kb][1], qhf[kb][2], qhf[kb][3], h0, h1);
                MMA_BF16(S[nb],   qhf[kb][0], qhf[kb][1], qhf[kb][2], qhf[kb][3], e0, e1);
                MMA_BF16(S[nb],   qlf[kb][0], qlf[kb][1], qlf[kb][2], qlf[kb][3], h0, h1);
                MMA_BF16(S[nb+1], qhf[kb][0], qhf[kb][1], qhf[kb][2], qhf[kb][3], h2, h3);
                MMA_BF16(S[nb+1], qhf[kb][0], qhf[kb][1], qhf[kb][2], qhf[kb][3], e2, e3);
                MMA_BF16(S[nb+1], qlf[kb][0], qlf[kb][1], qlf[kb][2], qlf[kb][3], h2, h3);
            }
        }

        // ---- exact softmax numerator: P = 2^(S*log2e/8); accumulate l ----
#pragma unroll
        for (int nb = 0; nb < 8; ++nb) {
            S[nb][0] = ex2f(S[nb][0] * SCALE);
            S[nb][1] = ex2f(S[nb][1] * SCALE);
            S[nb][2] = ex2f(S[nb][2] * SCALE);
            S[nb][3] = ex2f(S[nb][3] * SCALE);
            l0 += S[nb][0] + S[nb][1];
            l1 += S[nb][2] + S[nb][3];
        }

        // ---- O += P V  (bf16x3; x4 trans ldmatrix) ----
#pragma unroll
        for (int kb = 0; kb < 4; ++kb) {
            uint32_t phi[4], plo[4];
#pragma unroll
            for (int half = 0; half < 2; ++half) {
                const float c0 = S[2 * kb + half][0], c1 = S[2 * kb + half][1];
                const float c2 = S[2 * kb + half][2], c3 = S[2 * kb + half][3];
                __nv_bfloat162 h0 = __floats2bfloat162_rn(c0, c1);
                __nv_bfloat162 h1 = __floats2bfloat162_rn(c2, c3);
                __nv_bfloat162 e0 = __floats2bfloat162_rn(c0 - __bfloat162float(h0.x),
                                                          c1 - __bfloat162float(h0.y));
                __nv_bfloat162 e1 = __floats2bfloat162_rn(c2 - __bfloat162float(h1.x),
                                                          c3 - __bfloat162float(h1.y));
                phi[2 * half]     = *(uint32_t*)&h0;
                phi[2 * half + 1] = *(uint32_t*)&h1;
                plo[2 * half]     = *(uint32_t*)&e0;
                plo[2 * half + 1] = *(uint32_t*)&e1;
            }
#pragma unroll
            for (int nb = 0; nb < 8; nb += 2) {
                const uint32_t off = vx4 + (kb * 16 * TP + nb * 8) * 2;
                uint32_t vh0, vh1, vh2, vh3, vl0, vl1, vl2, vl3;
                LDSM_X4T(vh0, vh1, vh2, vh3, VhiB + off);
                LDSM_X4T(vl0, vl1, vl2, vl3, VloB + off);
                MMA_BF16(o_[nb],   phi[0], phi[1], phi[2], phi[3], vh0, vh1);
                MMA_BF16(o_[nb],   phi[0], phi[1], phi[2], phi[3], vl0, vl1);
                MMA_BF16(o_[nb],   plo[0], plo[1], plo[2], plo[3], vh0, vh1);
                MMA_BF16(o_[nb+1], phi[0], phi[1], phi[2], phi[3], vh2, vh3);
                MMA_BF16(o_[nb+1], phi[0], phi[1], phi[2], phi[3], vl2, vl3);
                MMA_BF16(o_[nb+1], plo[0], plo[1], plo[2], plo[3], vh2, vh3);
            }
        }
        __syncthreads();
        buf ^= 1;
    }

    // ---- epilogue: reduce l across quad, O /= l, tf32-round ----
    l0 += __shfl_xor_sync(0xffffffffu, l0, 1);
    l0 += __shfl_xor_sync(0xffffffffu, l0, 2);
    l1 += __shfl_xor_sync(0xffffffffu, l1, 1);
    l1 += __shfl_xor_sync(0xffffffffu, l1, 2);

    const int b = bh >> 4, h = bh & 15;
    const float inv0 = 1.f / l0, inv1 = 1.f / l1;
    const int row0 = q0 + (w << 4) + g;
#pragma unroll
    for (int nb = 0; nb < 8; ++nb) {
        const int col = h * HD_ + nb * 8 + 2 * t;
        float2 v0 = { rnd_tf32(o_[nb][0] * inv0), rnd_tf32(o_[nb][1] * inv0) };
        float2 v1 = { rnd_tf32(o_[nb][2] * inv1), rnd_tf32(o_[nb][3] * inv1) };
        *(float2*)(O + (size_t)(b * S_ + row0) * D_ + col)     = v0;
        *(float2*)(O + (size_t)(b * S_ + row0 + 8) * D_ + col) = v1;
    }
}

// ---------------- launch ----------------
extern "C" void kernel_launch(void* const* d_in, const int* in_sizes, int n_in,
                              void* d_out, int out_size)
{
    const float* x        = (const float*)d_in[0];
    const float* w_qkv    = (const float*)d_in[1];
    const float* b_qkv    = (const float*)d_in[2];
    const float* w_out    = (const float*)d_in[3];
    const float* b_out    = (const float*)d_in[4];
    const float* ln_scale = (const float*)d_in[5];
    const float* ln_bias  = (const float*)d_in[6];
    const float* q_scale  = (const float*)d_in[7];
    const float* k_scale  = (const float*)d_in[8];
    float* out = (float*)d_out;

    float *xn, *qkv, *attn, *wqt, *wot;
    float2* rtab;
    __nv_bfloat16 *qh, *ql, *kh, *kl, *vh, *vl;
    cudaGetSymbolAddress((void**)&xn,   g_xn);
    cudaGetSymbolAddress((void**)&qkv,  g_qkv);
    cudaGetSymbolAddress((void**)&attn, g_attn);
    cudaGetSymbolAddress((void**)&wqt,  g_wqt);
    cudaGetSymbolAddress((void**)&wot,  g_wot);
    cudaGetSymbolAddress((void**)&rtab, g_rtab);
    cudaGetSymbolAddress((void**)&qh,   g_qh);
    cudaGetSymbolAddress((void**)&ql,   g_ql);
    cudaGetSymbolAddress((void**)&kh,   g_kh);
    cudaGetSymbolAddress((void**)&kl,   g_kl);
    cudaGetSymbolAddress((void**)&vh,   g_vh);
    cudaGetSymbolAddress((void**)&vl,   g_vl);

    const int attn_smem = 2 * 4 * TSZ * sizeof(__nv_bfloat16);          // 73728 B
    const int gemm_smem = 3 * (128 * 20 + 16 * 136) * sizeof(uint32_t); // 56832 B
    cudaFuncSetAttribute(attn_kernel, cudaFuncAttributeMaxDynamicSharedMemorySize, attn_smem);
    cudaFuncSetAttribute(tf32_gemm_bias, cudaFuncAttributeMaxDynamicSharedMemorySize, gemm_smem);

    cvt_tf32_kernel<<<(D_ * 3 * D_) / 1024, 256>>>(w_qkv, wqt);
    cvt_tf32_kernel<<<(D_ * D_) / 1024, 256>>>(w_out, wot);
    rope_tab_kernel<<<(S_ * 32) / 256, 256>>>(rtab);
    ln_kernel<<<ROWS_, 256>>>(x, ln_scale, ln_bias, xn);
    tf32_gemm_bias<<<dim3((3 * D_) / 128, ROWS_ / 128), 256, gemm_smem>>>(
        xn, wqt, b_qkv, qkv, ROWS_, 3 * D_, D_);
    qk_rope_kernel<<<ROWS_, 512>>>(qkv, rtab, q_scale, k_scale, qh, ql, kh, kl, vh, vl);
    attn_kernel<<<dim3(S_ / 64, B_ * H_), 128, attn_smem>>>(qh, ql, kh, kl, vh, vl, attn);
    tf32_gemm_bias<<<dim3(D_ / 128, ROWS_ / 128), 256, gemm_smem>>>(
        attn, wot, b_out, out, ROWS_, D_, D_);
}

// round 10
// speedup vs baseline: 3.7241x; 1.0120x over previous
#include <cuda_runtime.h>
#include <cuda_bf16.h>
#include <stdint.h>
#include <math.h>

#define B_  2
#define S_  2048
#define D_  1024
#define H_  16
#define HD_ 64
#define ROWS_ (B_*S_)   // 4096

// ---------------- scratch (device globals; no allocations) ----------------
__device__ float g_xn  [ROWS_*D_];
__device__ float g_qkv [ROWS_*3*D_];
__device__ float g_attn[ROWS_*D_];
__device__ float g_wqt [D_*3*D_];     // tf32-rounded w_qkv
__device__ float g_wot [D_*D_];       // tf32-rounded w_out
__device__ float2 g_rtab[S_*32];      // RoPE cos/sin table
__device__ __nv_bfloat16 g_qh[B_*H_*S_*HD_];
__device__ __nv_bfloat16 g_ql[B_*H_*S_*HD_];
__device__ __nv_bfloat16 g_kh[B_*H_*S_*HD_];
__device__ __nv_bfloat16 g_kl[B_*H_*S_*HD_];
__device__ __nv_bfloat16 g_vh[B_*H_*S_*HD_];
__device__ __nv_bfloat16 g_vl[B_*H_*S_*HD_];

// ---------------- helpers ----------------
__device__ __forceinline__ uint32_t f2tf32(float x) {
    uint32_t r;
    asm("cvt.rna.tf32.f32 %0, %1;" : "=r"(r) : "f"(x));
    return r;
}
__device__ __forceinline__ float rnd_tf32(float x) {
    return __uint_as_float(f2tf32(x));
}

#define MMA_TF32(d, a, b)                                              \
    asm volatile("mma.sync.aligned.m16n8k8.row.col.f32.tf32.tf32.f32 " \
        "{%0,%1,%2,%3}, {%4,%5,%6,%7}, {%8,%9}, {%0,%1,%2,%3};"        \
        : "+f"((d)[0]), "+f"((d)[1]), "+f"((d)[2]), "+f"((d)[3])       \
        : "r"((a)[0]), "r"((a)[1]), "r"((a)[2]), "r"((a)[3]),          \
          "r"((b)[0]), "r"((b)[1]))

#define CP16(dst, src)                                                     \
    asm volatile("cp.async.ca.shared.global [%0], [%1], 16;"               \
        :: "r"(dst), "l"(src))
#define CP_COMMIT()  asm volatile("cp.async.commit_group;")
#define CP_WAIT(n)   asm volatile("cp.async.wait_group %0;" :: "n"(n))

// ---------------- kernel 0a: tf32-round a float array ----------------
__global__ __launch_bounds__(256) void cvt_tf32_kernel(
    const float* __restrict__ in, float* __restrict__ out)
{
    const int i = blockIdx.x * 256 + threadIdx.x;
    float4 v = ((const float4*)in)[i];
    v.x = rnd_tf32(v.x); v.y = rnd_tf32(v.y);
    v.z = rnd_tf32(v.z); v.w = rnd_tf32(v.w);
    ((float4*)out)[i] = v;
}

// ---------------- kernel 0b: RoPE table (fp64 once per (s,freq)) ----------
__global__ __launch_bounds__(256) void rope_tab_kernel(float2* __restrict__ tab)
{
    const int i = blockIdx.x * 256 + threadIdx.x;   // 0..65535
    const int s = i >> 5, f = i & 31;
    double invf = exp(-0.28782313662425575 * (double)f); // ln(10000)/32
    double sn, cs;
    sincos((double)s * invf, &sn, &cs);
    tab[i] = make_float2((float)cs, (float)sn);
}

// ---------------- kernel 1: LayerNorm (emits tf32-rounded xn) ----------------
__global__ __launch_bounds__(256) void ln_kernel(
    const float* __restrict__ x, const float* __restrict__ g,
    const float* __restrict__ b, float* __restrict__ y)
{
    __shared__ float red[16];
    const int row = blockIdx.x, tid = threadIdx.x;
    const float* xr = x + (size_t)row * D_;
    float4 v = *(const float4*)(xr + (tid << 2));
    float s  = v.x + v.y + v.z + v.w;
    float ss = v.x*v.x + v.y*v.y + v.z*v.z + v.w*v.w;
#pragma unroll
    for (int off = 16; off; off >>= 1) {
        s  += __shfl_xor_sync(0xffffffffu, s,  off);
        ss += __shfl_xor_sync(0xffffffffu, ss, off);
    }
    if ((tid & 31) == 0) { red[tid >> 5] = s; red[8 + (tid >> 5)] = ss; }
    __syncthreads();
    if (tid < 8) {
        float a = red[tid], c = red[8 + tid];
#pragma unroll
        for (int off = 4; off; off >>= 1) {
            a += __shfl_xor_sync(0xffu, a, off);
            c += __shfl_xor_sync(0xffu, c, off);
        }
        if (tid == 0) { red[0] = a; red[8] = c; }
    }
    __syncthreads();
    const float mean = red[0] * (1.f / 1024.f);
    const float var  = red[8] * (1.f / 1024.f) - mean * mean;
    const float r    = rsqrtf(var + 1e-6f);
    float4 gv = *(const float4*)(g + (tid << 2));
    float4 bv = *(const float4*)(b + (tid << 2));
    float4 o;
    o.x = rnd_tf32((v.x - mean) * r * gv.x + bv.x);
    o.y = rnd_tf32((v.y - mean) * r * gv.y + bv.y);
    o.z = rnd_tf32((v.z - mean) * r * gv.z + bv.z);
    o.w = rnd_tf32((v.w - mean) * r * gv.w + bv.w);
    *(float4*)(y + (size_t)row * D_ + (tid << 2)) = o;
}

// ---------------- kernel 2/5: tf32 GEMM + bias, cp.async 3-stage ----------
__global__ __launch_bounds__(256) void tf32_gemm_bias(
    const float* __restrict__ A, const float* __restrict__ Bm,
    const float* __restrict__ bias, float* __restrict__ C,
    int M, int N, int K)
{
    constexpr int AP = 20, BP = 136;
    constexpr int ASZ = 128 * AP;
    constexpr int BSZ = 16 * BP;
    extern __shared__ uint32_t gsm[];
    uint32_t* As = gsm;
    uint32_t* Bs = gsm + 3 * ASZ;

    const int tid  = threadIdx.x;
    const int wid  = tid >> 5, lane = tid & 31;
    const int g    = lane >> 2, t = lane & 3;
    const int wm   = wid & 1;
    const int wn   = wid >> 1;
    const int m0   = blockIdx.y << 7, n0 = blockIdx.x << 7;

    const uint32_t smemB = (uint32_t)__cvta_generic_to_shared(gsm);

    float acc[4][4][4];
#pragma unroll
    for (int mi = 0; mi < 4; mi++)
#pragma unroll
        for (int ni = 0; ni < 4; ni++)
#pragma unroll
            for (int r = 0; r < 4; r++) acc[mi][ni][r] = 0.f;

    auto load_stage = [&](int st, int ks) {
        const float* Asrc = A  + (size_t)m0 * K + ks * 16;
        const float* Bsrc = Bm + (size_t)(ks * 16) * N + n0;
        const uint32_t aB = smemB + (st * ASZ) * 4;
        const uint32_t bB = smemB + (3 * ASZ + st * BSZ) * 4;
#pragma unroll
        for (int it = 0; it < 2; ++it) {
            const int c  = tid + (it << 8);
            const int ar = c >> 2,  ak = (c & 3) << 2;
            CP16(aB + (ar * AP + ak) * 4, Asrc + (size_t)ar * K + ak);
            const int br = c >> 5,  bc = (c & 31) << 2;
            CP16(bB + (br * BP + bc) * 4, Bsrc + (size_t)br * N + bc);
        }
    };

    load_stage(0, 0); CP_COMMIT();
    load_stage(1, 1); CP_COMMIT();

    const int KSTEPS = K >> 4;
    for (int ks = 0; ks < KSTEPS; ++ks) {
        CP_WAIT(1);
        __syncthreads();
        const int buf = ks % 3;
        const uint32_t* Ab = As + buf * ASZ;
        const uint32_t* Bb = Bs + buf * BSZ;

#pragma unroll
        for (int kk = 0; kk < 16; kk += 8) {
            uint32_t af[4][4], bfr[4][2];
#pragma unroll
            for (int mi = 0; mi < 4; mi++) {
                const int rb = wm * 64 + mi * 16;
                af[mi][0] = Ab[(rb + g)     * AP + kk + t];
                af[mi][1] = Ab[(rb + 8 + g) * AP + kk + t];
                af[mi][2] = Ab[(rb + g)     * AP + kk + t + 4];
                af[mi][3] = Ab[(rb + 8 + g) * AP + kk + t + 4];
            }
#pragma unroll
            for (int ni = 0; ni < 4; ni++) {
                const int cb = wn * 32 + ni * 8 + g;
                bfr[ni][0] = Bb[(kk + t)     * BP + cb];
                bfr[ni][1] = Bb[(kk + t + 4) * BP + cb];
            }
#pragma unroll
            for (int mi = 0; mi < 4; mi++)
#pragma unroll
                for (int ni = 0; ni < 4; ni++)
                    MMA_TF32(acc[mi][ni], af[mi], bfr[ni]);
        }

        if (ks + 2 < KSTEPS) load_stage((ks + 2) % 3, ks + 2);
        CP_COMMIT();
    }

#pragma unroll
    for (int mi = 0; mi < 4; mi++) {
        const int row0 = m0 + wm * 64 + mi * 16 + g;
#pragma unroll
        for (int ni = 0; ni < 4; ni++) {
            const int col = n0 + wn * 32 + ni * 8 + 2 * t;
            float2 bb = *(const float2*)(bias + col);
            float2 v0 = { acc[mi][ni][0] + bb.x, acc[mi][ni][1] + bb.y };
            float2 v1 = { acc[mi][ni][2] + bb.x, acc[mi][ni][3] + bb.y };
            *(float2*)(C + (size_t)row0 * N + col)       = v0;
            *(float2*)(C + (size_t)(row0 + 8) * N + col) = v1;
        }
    }
}

// ---------------- kernel 3: per-head LN + RoPE -> bf16 hi/lo ----------------
__device__ __forceinline__ float warp_allreduce_sum(float v) {
#pragma unroll
    for (int off = 16; off; off >>= 1) v += __shfl_xor_sync(0xffffffffu, v, off);
    return v;
}

__device__ __forceinline__ void split_store(
    __nv_bfloat16* hi, __nv_bfloat16* lo, size_t idx, float x)
{
    __nv_bfloat16 h = __float2bfloat16_rn(x);
    hi[idx] = h;
    lo[idx] = __float2bfloat16_rn(x - __bfloat162float(h));
}

__global__ __launch_bounds__(512) void qk_rope_kernel(
    const float* __restrict__ qkv, const float2* __restrict__ tab,
    const float* __restrict__ qsc, const float* __restrict__ ksc,
    __nv_bfloat16* __restrict__ Qh, __nv_bfloat16* __restrict__ Ql,
    __nv_bfloat16* __restrict__ Kh, __nv_bfloat16* __restrict__ Kl,
    __nv_bfloat16* __restrict__ Vh, __nv_bfloat16* __restrict__ Vl)
{
    const int bs   = blockIdx.x;
    const int b    = bs >> 11;
    const int s    = bs & (S_ - 1);
    const int h    = threadIdx.x >> 5;
    const int lane = threadIdx.x & 31;
    const float* base = qkv + (size_t)bs * (3 * D_) + h * HD_;

    float q0 = base[lane],        q1 = base[lane + 32];
    float k0 = base[1024 + lane], k1 = base[1024 + lane + 32];
    float v0 = base[2048 + lane], v1 = base[2048 + lane + 32];

    float mu  = warp_allreduce_sum(q0 + q1) * (1.f / 64.f);
    float d0  = q0 - mu, d1 = q1 - mu;
    float var = warp_allreduce_sum(d0*d0 + d1*d1) * (1.f / 64.f);
    float r   = rsqrtf(var + 1e-6f);
    float qn0 = d0 * r * qsc[lane];
    float qn1 = d1 * r * qsc[lane + 32];

    mu  = warp_allreduce_sum(k0 + k1) * (1.f / 64.f);
    d0  = k0 - mu; d1 = k1 - mu;
    var = warp_allreduce_sum(d0*d0 + d1*d1) * (1.f / 64.f);
    r   = rsqrtf(var + 1e-6f);
    float kn0 = d0 * r * ksc[lane];
    float kn1 = d1 * r * ksc[lane + 32];

    const float2 cs = tab[(s << 5) + lane];
    const float c = cs.x, si = cs.y;

    float qr0 = qn0 * c - qn1 * si;
    float qr1 = qn1 * c + qn0 * si;
    float kr0 = kn0 * c - kn1 * si;
    float kr1 = kn1 * c + kn0 * si;

    const size_t o = (((size_t)(b * H_ + h)) * S_ + s) * HD_ + lane;
    split_store(Qh, Ql, o,      qr0);
    split_store(Qh, Ql, o + 32, qr1);
    split_store(Kh, Kl, o,      kr0);
    split_store(Kh, Kl, o + 32, kr1);
    split_store(Vh, Vl, o,      v0);
    split_store(Vh, Vl, o + 32, v1);
}

// ---------------- bf16 mma helpers for attention ----------------
#define LDSM_X4(r0,r1,r2,r3,addr)                                          \
    asm volatile("ldmatrix.sync.aligned.m8n8.x4.shared.b16 {%0,%1,%2,%3}, [%4];" \
        : "=r"(r0), "=r"(r1), "=r"(r2), "=r"(r3) : "r"(addr))

#define LDSM_X4T(r0,r1,r2,r3,addr)                                         \
    asm volatile("ldmatrix.sync.aligned.m8n8.x4.trans.shared.b16 {%0,%1,%2,%3}, [%4];" \
        : "=r"(r0), "=r"(r1), "=r"(r2), "=r"(r3) : "r"(addr))

#define MMA_BF16(d, a0,a1,a2,a3, b0,b1)                                    \
    asm volatile("mma.sync.aligned.m16n8k16.row.col.f32.bf16.bf16.f32 "    \
        "{%0,%1,%2,%3}, {%4,%5,%6,%7}, {%8,%9}, {%0,%1,%2,%3};"            \
        : "+f"((d)[0]), "+f"((d)[1]), "+f"((d)[2]), "+f"((d)[3])           \
        : "r"(a0), "r"(a1), "r"(a2), "r"(a3), "r"(b0), "r"(b1))

__device__ __forceinline__ float ex2f(float x) {
    float y; asm("ex2.approx.f32 %0, %1;" : "=f"(y) : "f"(x)); return y;
}

#define TP 72
#define TSZ (64 * TP)          // halfs per 64x64 tile

__device__ __forceinline__ void cp_tile(
    uint32_t dst, const __nv_bfloat16* __restrict__ src, int tid)
{
#pragma unroll
    for (int it = 0; it < 4; ++it) {
        int c = tid + (it << 7);       // 0..511 chunks of 16B
        int r = c >> 3, cc = c & 7;
        CP16(dst + r * (TP * 2) + cc * 16, src + r * HD_ + cc * 8);
    }
}

// ---------------- kernel 4: flash attention (bf16x3, 128-row Q tile) -------
// 4 warps, each owns 32 q-rows (two 16-row A-frag sets). Every K/V ldmatrix
// feeds 2x MMA work vs the 64-row version -> smem traffic per FLOP halved.
// No-max softmax (scores bounded by 8; see R9 derivation).
__global__ __launch_bounds__(128, 2) void attn_kernel(
    const __nv_bfloat16* __restrict__ Qh, const __nv_bfloat16* __restrict__ Ql,
    const __nv_bfloat16* __restrict__ Kh, const __nv_bfloat16* __restrict__ Kl,
    const __nv_bfloat16* __restrict__ Vh, const __nv_bfloat16* __restrict__ Vl,
    float* __restrict__ O)
{
    extern __shared__ __nv_bfloat16 sh[];   // [2 stages][4 tiles][TSZ]

    const int tid  = threadIdx.x;
    const int lane = tid & 31, w = tid >> 5;
    const int g    = lane >> 2, t = lane & 3;
    const int bh   = blockIdx.y;
    const int q0   = blockIdx.x << 7;       // 128-row Q tile

    const __nv_bfloat16* Kbh = Kh + (size_t)bh * S_ * HD_;
    const __nv_bfloat16* Kbl = Kl + (size_t)bh * S_ * HD_;
    const __nv_bfloat16* Vbh = Vh + (size_t)bh * S_ * HD_;
    const __nv_bfloat16* Vbl = Vl + (size_t)bh * S_ * HD_;

    const uint32_t shB = (uint32_t)__cvta_generic_to_shared(sh);

    // ---- Q A-fragments straight from gmem (once); two 16-row halves ----
    uint32_t qhf[2][4][4], qlf[2][4][4];
#pragma unroll
    for (int hf = 0; hf < 2; ++hf) {
        const __nv_bfloat16* Qbase = Qh + ((size_t)bh * S_ + q0 + (w << 5) + hf * 16) * HD_;
        const __nv_bfloat16* Qbl   = Ql + ((size_t)bh * S_ + q0 + (w << 5) + hf * 16) * HD_;
#pragma unroll
        for (int kb = 0; kb < 4; ++kb) {
            const int c0 = kb * 16 + 2 * t;
            qhf[hf][kb][0] = *(const uint32_t*)(Qbase + (size_t)g       * HD_ + c0);
            qhf[hf][kb][1] = *(const uint32_t*)(Qbase + (size_t)(g + 8) * HD_ + c0);
            qhf[hf][kb][2] = *(const uint32_t*)(Qbase + (size_t)g       * HD_ + c0 + 8);
            qhf[hf][kb][3] = *(const uint32_t*)(Qbase + (size_t)(g + 8) * HD_ + c0 + 8);
            qlf[hf][kb][0] = *(const uint32_t*)(Qbl   + (size_t)g       * HD_ + c0);
            qlf[hf][kb][1] = *(const uint32_t*)(Qbl   + (size_t)(g + 8) * HD_ + c0);
            qlf[hf][kb][2] = *(const uint32_t*)(Qbl   + (size_t)g       * HD_ + c0 + 8);
            qlf[hf][kb][3] = *(const uint32_t*)(Qbl   + (size_t)(g + 8) * HD_ + c0 + 8);
        }
    }

    const uint32_t kx4 = ((((lane >> 4) << 3) + (lane & 7)) * TP
                          + ((lane >> 3) & 1) * 8) * 2;
    const uint32_t vx4 = (((((lane >> 3) & 1) << 3) + (lane & 7)) * TP
                          + ((lane >> 4) & 1) * 8) * 2;

    float lsum[2][2] = {{0.f, 0.f}, {0.f, 0.f}};
    float o_[2][8][4];
#pragma unroll
    for (int hf = 0; hf < 2; hf++)
#pragma unroll
        for (int nb = 0; nb < 8; nb++)
#pragma unroll
            for (int j = 0; j < 4; j++) o_[hf][nb][j] = 0.f;

    const float SCALE = 0.18033688011112042f;  // log2(e)/8

    {
        const uint32_t st0 = shB;
        cp_tile(st0,                Kbh, tid);
        cp_tile(st0 + TSZ * 2,      Kbl, tid);
        cp_tile(st0 + 2 * TSZ * 2,  Vbh, tid);
        cp_tile(st0 + 3 * TSZ * 2,  Vbl, tid);
        CP_COMMIT();
    }

    int buf = 0;
    for (int kt = 0; kt < S_; kt += 64) {
        if (kt + 64 < S_) {
            const uint32_t stn = shB + (buf ^ 1) * 4 * TSZ * 2;
            const size_t goff = (size_t)(kt + 64) * HD_;
            cp_tile(stn,               Kbh + goff, tid);
            cp_tile(stn + TSZ * 2,     Kbl + goff, tid);
            cp_tile(stn + 2 * TSZ * 2, Vbh + goff, tid);
            cp_tile(stn + 3 * TSZ * 2, Vbl + goff, tid);
            CP_COMMIT();
            CP_WAIT(1);
        } else {
            CP_WAIT(0);
        }
        __syncthreads();

        const uint32_t KhiB = shB + buf * 4 * TSZ * 2;
        const uint32_t KloB = KhiB + TSZ * 2;
        const uint32_t VhiB = KhiB + 2 * TSZ * 2;
        const uint32_t VloB = KhiB + 3 * TSZ * 2;

        // ---- S = Q K^T for both 16-row halves; K ldmatrix shared ----
        float S[2][8][4];
#pragma unroll
        for (int hf = 0; hf < 2; hf++)
#pragma unroll
            for (int nb = 0; nb < 8; nb++)
#pragma unroll
                for (int j = 0; j < 4; j++) S[hf][nb][j] = 0.f;

#pragma unroll
        for (int nb = 0; nb < 8; nb += 2) {
#pragma unroll
            for (int kb = 0; kb < 4; ++kb) {
                const uint32_t off = kx4 + (nb * 8 * TP + kb * 16) * 2;
                uint32_t h0, h1, h2, h3, e0, e1, e2, e3;
                LDSM_X4(h0, h1, h2, h3, KhiB + off);
                LDSM_X4(e0, e1, e2, e3, KloB + off);
#pragma unroll
                for (int hf = 0; hf < 2; ++hf) {
                    MMA_BF16(S[hf][nb],   qhf[hf][kb][0], qhf[hf][kb][1], qhf[hf][kb][2], qhf[hf][kb][3], h0, h1);
                    MMA_BF16(S[hf][nb],   qhf[hf][kb][0], qhf[hf][kb][1], qhf[hf][kb][2], qhf[hf][kb][3], e0, e1);
                    MMA_BF16(S[hf][nb],   qlf[hf][kb][0], qlf[hf][kb][1], qlf[hf][kb][2], qlf[hf][kb][3], h0, h1);
                    MMA_BF16(S[hf][nb+1], qhf[hf][kb][0], qhf[hf][kb][1], qhf[hf][kb][2], qhf[hf][kb][3], h2, h3);
                    MMA_BF16(S[hf][nb+1], qhf[hf][kb][0], qhf[hf][kb][1], qhf[hf][kb][2], qhf[hf][kb][3], e2, e3);
                    MMA_BF16(S[hf][nb+1], qlf[hf][kb][0], qlf[hf][kb][1], qlf[hf][kb][2], qlf[hf][kb][3], h2, h3);
                }
            }
        }

        // ---- exact softmax numerator: P = 2^(S*log2e/8); accumulate l ----
#pragma unroll
        for (int hf = 0; hf < 2; ++hf)
#pragma unroll
            for (int nb = 0; nb < 8; ++nb) {
                S[hf][nb][0] = ex2f(S[hf][nb][0] * SCALE);
                S[hf][nb][1] = ex2f(S[hf][nb][1] * SCALE);
                S[hf][nb][2] = ex2f(S[hf][nb][2] * SCALE);
                S[hf][nb][3] = ex2f(S[hf][nb][3] * SCALE);
                lsum[hf][0] += S[hf][nb][0] + S[hf][nb][1];
                lsum[hf][1] += S[hf][nb][2] + S[hf][nb][3];
            }

        // ---- O += P V, both halves; V ldmatrix shared ----
#pragma unroll
        for (int kb = 0; kb < 4; ++kb) {
            uint32_t phi[2][4], plo[2][4];
#pragma unroll
            for (int hf = 0; hf < 2; ++hf)
#pragma unroll
                for (int half = 0; half < 2; ++half) {
                    const float c0 = S[hf][2 * kb + half][0], c1 = S[hf][2 * kb + half][1];
                    const float c2 = S[hf][2 * kb + half][2], c3 = S[hf][2 * kb + half][3];
                    __nv_bfloat162 h0 = __floats2bfloat162_rn(c0, c1);
                    __nv_bfloat162 h1 = __floats2bfloat162_rn(c2, c3);
                    __nv_bfloat162 e0 = __floats2bfloat162_rn(c0 - __bfloat162float(h0.x),
                                                              c1 - __bfloat162float(h0.y));
                    __nv_bfloat162 e1 = __floats2bfloat162_rn(c2 - __bfloat162float(h1.x),
                                                              c3 - __bfloat162float(h1.y));
                    phi[hf][2 * half]     = *(uint32_t*)&h0;
                    phi[hf][2 * half + 1] = *(uint32_t*)&h1;
                    plo[hf][2 * half]     = *(uint32_t*)&e0;
                    plo[hf][2 * half + 1] = *(uint32_t*)&e1;
                }
#pragma unroll
            for (int nb = 0; nb < 8; nb += 2) {
                const uint32_t off = vx4 + (kb * 16 * TP + nb * 8) * 2;
                uint32_t vh0, vh1, vh2, vh3, vl0, vl1, vl2, vl3;
                LDSM_X4T(vh0, vh1, vh2, vh3, VhiB + off);
                LDSM_X4T(vl0, vl1, vl2, vl3, VloB + off);
#pragma unroll
                for (int hf = 0; hf < 2; ++hf) {
                    MMA_BF16(o_[hf][nb],   phi[hf][0], phi[hf][1], phi[hf][2], phi[hf][3], vh0, vh1);
                    MMA_BF16(o_[hf][nb],   phi[hf][0], phi[hf][1], phi[hf][2], phi[hf][3], vl0, vl1);
                    MMA_BF16(o_[hf][nb],   plo[hf][0], plo[hf][1], plo[hf][2], plo[hf][3], vh0, vh1);
                    MMA_BF16(o_[hf][nb+1], phi[hf][0], phi[hf][1], phi[hf][2], phi[hf][3], vh2, vh3);
                    MMA_BF16(o_[hf][nb+1], phi[hf][0], phi[hf][1], phi[hf][2], phi[hf][3], vl2, vl3);
                    MMA_BF16(o_[hf][nb+1], plo[hf][0], plo[hf][1], plo[hf][2], plo[hf][3], vh2, vh3);
                }
            }
        }
        __syncthreads();
        buf ^= 1;
    }

    // ---- epilogue: reduce l across quad, O /= l, tf32-round ----
    const int b = bh >> 4, h = bh & 15;
#pragma unroll
    for (int hf = 0; hf < 2; ++hf) {
        float l0 = lsum[hf][0], l1 = lsum[hf][1];
        l0 += __shfl_xor_sync(0xffffffffu, l0, 1);
        l0 += __shfl_xor_sync(0xffffffffu, l0, 2);
        l1 += __shfl_xor_sync(0xffffffffu, l1, 1);
        l1 += __shfl_xor_sync(0xffffffffu, l1, 2);
        const float inv0 = 1.f / l0, inv1 = 1.f / l1;
        const int row0 = q0 + (w << 5) + hf * 16 + g;
#pragma unroll
        for (int nb = 0; nb < 8; ++nb) {
            const int col = h * HD_ + nb * 8 + 2 * t;
            float2 v0 = { rnd_tf32(o_[hf][nb][0] * inv0), rnd_tf32(o_[hf][nb][1] * inv0) };
            float2 v1 = { rnd_tf32(o_[hf][nb][2] * inv1), rnd_tf32(o_[hf][nb][3] * inv1) };
            *(float2*)(O + (size_t)(b * S_ + row0) * D_ + col)     = v0;
            *(float2*)(O + (size_t)(b * S_ + row0 + 8) * D_ + col) = v1;
        }
    }
}

// ---------------- launch ----------------
extern "C" void kernel_launch(void* const* d_in, const int* in_sizes, int n_in,
                              void* d_out, int out_size)
{
    const float* x        = (const float*)d_in[0];
    const float* w_qkv    = (const float*)d_in[1];
    const float* b_qkv    = (const float*)d_in[2];
    const float* w_out    = (const float*)d_in[3];
    const float* b_out    = (const float*)d_in[4];
    const float* ln_scale = (const float*)d_in[5];
    const float* ln_bias  = (const float*)d_in[6];
    const float* q_scale  = (const float*)d_in[7];
    const float* k_scale  = (const float*)d_in[8];
    float* out = (float*)d_out;

    float *xn, *qkv, *attn, *wqt, *wot;
    float2* rtab;
    __nv_bfloat16 *qh, *ql, *kh, *kl, *vh, *vl;
    cudaGetSymbolAddress((void**)&xn,   g_xn);
    cudaGetSymbolAddress((void**)&qkv,  g_qkv);
    cudaGetSymbolAddress((void**)&attn, g_attn);
    cudaGetSymbolAddress((void**)&wqt,  g_wqt);
    cudaGetSymbolAddress((void**)&wot,  g_wot);
    cudaGetSymbolAddress((void**)&rtab, g_rtab);
    cudaGetSymbolAddress((void**)&qh,   g_qh);
    cudaGetSymbolAddress((void**)&ql,   g_ql);
    cudaGetSymbolAddress((void**)&kh,   g_kh);
    cudaGetSymbolAddress((void**)&kl,   g_kl);
    cudaGetSymbolAddress((void**)&vh,   g_vh);
    cudaGetSymbolAddress((void**)&vl,   g_vl);

    const int attn_smem = 2 * 4 * TSZ * sizeof(__nv_bfloat16);          // 73728 B
    const int gemm_smem = 3 * (128 * 20 + 16 * 136) * sizeof(uint32_t); // 56832 B
    cudaFuncSetAttribute(attn_kernel, cudaFuncAttributeMaxDynamicSharedMemorySize, attn_smem);
    cudaFuncSetAttribute(tf32_gemm_bias, cudaFuncAttributeMaxDynamicSharedMemorySize, gemm_smem);

    cvt_tf32_kernel<<<(D_ * 3 * D_) / 1024, 256>>>(w_qkv, wqt);
    cvt_tf32_kernel<<<(D_ * D_) / 1024, 256>>>(w_out, wot);
    rope_tab_kernel<<<(S_ * 32) / 256, 256>>>(rtab);
    ln_kernel<<<ROWS_, 256>>>(x, ln_scale, ln_bias, xn);
    tf32_gemm_bias<<<dim3((3 * D_) / 128, ROWS_ / 128), 256, gemm_smem>>>(
        xn, wqt, b_qkv, qkv, ROWS_, 3 * D_, D_);
    qk_rope_kernel<<<ROWS_, 512>>>(qkv, rtab, q_scale, k_scale, qh, ql, kh, kl, vh, vl);
    attn_kernel<<<dim3(S_ / 128, B_ * H_), 128, attn_smem>>>(qh, ql, kh, kl, vh, vl, attn);
    tf32_gemm_bias<<<dim3(D_ / 128, ROWS_ / 128), 256, gemm_smem>>>(
        attn, wot, b_out, out, ROWS_, D_, D_);
}